// round 2
// baseline (speedup 1.0000x reference)
#include <cuda_runtime.h>

// Problem constants
#define B_  4
#define S_  2048
#define D_  768
#define H_  12
#define DK_ 64
#define M_TOT (B_ * S_)     // 8192 rows for projection GEMMs

// Scratch (device globals — no allocation allowed in kernel_launch)
__device__ float g_q[(size_t)B_ * H_ * S_ * DK_];   // (B,H,S,DK)
__device__ float g_k[(size_t)B_ * H_ * S_ * DK_];
__device__ float g_v[(size_t)B_ * H_ * S_ * DK_];
__device__ float g_x[(size_t)B_ * S_ * D_];         // attention out, merged heads (B,S,D)

// ---------------------------------------------------------------------------
// GEMM: Y[m,n] = sum_k X[m,k] * W[n,k] + bias[n]
// X: (M, 768) row-major, W: (768, 768) row-major (nn.Linear weight), M = 8192.
// scatter=1 -> write to (B,H,S,DK) layout (head split); scatter=0 -> row-major.
// Tile 64x64x16, 256 threads, 4x4 per-thread microtile.
// ---------------------------------------------------------------------------
__global__ __launch_bounds__(256) void gemm_kernel(
    const float* __restrict__ X, const float* __restrict__ W,
    const float* __restrict__ bias, float* __restrict__ out, int scatter)
{
    __shared__ float sX[16][64];
    __shared__ float sW[16][64];

    const int tid = threadIdx.x;
    const int tx = tid & 15;       // 0..15 -> n micro
    const int ty = tid >> 4;       // 0..15 -> m micro
    const int m0 = blockIdx.y * 64;
    const int n0 = blockIdx.x * 64;

    float acc[4][4] = {};

    const int r  = tid >> 2;       // 0..63 row within tile
    const int c4 = tid & 3;        // 0..3  float4 column group

    for (int k0 = 0; k0 < D_; k0 += 16) {
        float4 xv = *(const float4*)(X + (size_t)(m0 + r) * D_ + k0 + c4 * 4);
        float4 wv = *(const float4*)(W + (size_t)(n0 + r) * D_ + k0 + c4 * 4);
        sX[c4 * 4 + 0][r] = xv.x; sX[c4 * 4 + 1][r] = xv.y;
        sX[c4 * 4 + 2][r] = xv.z; sX[c4 * 4 + 3][r] = xv.w;
        sW[c4 * 4 + 0][r] = wv.x; sW[c4 * 4 + 1][r] = wv.y;
        sW[c4 * 4 + 2][r] = wv.z; sW[c4 * 4 + 3][r] = wv.w;
        __syncthreads();

        #pragma unroll
        for (int kk = 0; kk < 16; kk++) {
            float4 a = *(const float4*)&sX[kk][ty * 4];
            float4 b = *(const float4*)&sW[kk][tx * 4];
            acc[0][0] += a.x * b.x; acc[0][1] += a.x * b.y; acc[0][2] += a.x * b.z; acc[0][3] += a.x * b.w;
            acc[1][0] += a.y * b.x; acc[1][1] += a.y * b.y; acc[1][2] += a.y * b.z; acc[1][3] += a.y * b.w;
            acc[2][0] += a.z * b.x; acc[2][1] += a.z * b.y; acc[2][2] += a.z * b.z; acc[2][3] += a.z * b.w;
            acc[3][0] += a.w * b.x; acc[3][1] += a.w * b.y; acc[3][2] += a.w * b.z; acc[3][3] += a.w * b.w;
        }
        __syncthreads();
    }

    #pragma unroll
    for (int i = 0; i < 4; i++) {
        const int m = m0 + ty * 4 + i;
        #pragma unroll
        for (int j = 0; j < 4; j++) {
            const int n = n0 + tx * 4 + j;
            const float v = acc[i][j] + bias[n];
            if (scatter) {
                const int bb = m >> 11;      // m / S_
                const int s  = m & 2047;     // m % S_
                const int h  = n >> 6;       // n / DK_
                const int dk = n & 63;       // n % DK_
                out[((((size_t)bb * H_ + h) * S_) + s) * DK_ + dk] = v;
            } else {
                out[(size_t)m * D_ + n] = v;
            }
        }
    }
}

// ---------------------------------------------------------------------------
// Flash-attention style kernel.
// Grid: (S/64, H, B). Block: 256 threads. 64 queries x 64 keys per inner tile.
// Online softmax with running (m, l); O accumulator (4x4 per thread) in regs.
// Writes merged-head layout g_x[(b*S+q)*D + h*DK + d].
// ---------------------------------------------------------------------------
#define ATTN_SMEM_FLOATS (4096 * 3 + 64 * 65 + 64 * 3 + 64)
#define ATTN_SMEM_BYTES  (ATTN_SMEM_FLOATS * 4)

__global__ __launch_bounds__(256) void attn_kernel(
    const float* __restrict__ gq, const float* __restrict__ gk,
    const float* __restrict__ gv, const int* __restrict__ mask,
    float* __restrict__ gx)
{
    extern __shared__ float sm[];
    float* sQ = sm;                 // [64][64]
    float* sK = sm + 4096;          // [64][64]
    float* sV = sm + 8192;          // [64][64]
    float* sS = sm + 12288;         // [64][65] (padded)
    float* sM = sm + 12288 + 4160;  // [64] running max
    float* sL = sM + 64;            // [64] running sum
    float* sC = sL + 64;            // [64] correction
    int*   sMask = (int*)(sC + 64); // [64]

    const int tid = threadIdx.x;
    const int tx = tid & 15;
    const int ty = tid >> 4;
    const int q0 = blockIdx.x * 64;
    const int h  = blockIdx.y;
    const int b  = blockIdx.z;

    const size_t head_base = (((size_t)b * H_ + h) * S_) * DK_;
    const float* Qh = gq + head_base;
    const float* Kh = gk + head_base;
    const float* Vh = gv + head_base;

    // Load Q tile: contiguous 64*64 floats
    {
        const float4* src = (const float4*)(Qh + (size_t)q0 * DK_);
        float4* dst = (float4*)sQ;
        #pragma unroll
        for (int i = 0; i < 4; i++) dst[tid + 256 * i] = src[tid + 256 * i];
    }
    if (tid < 64) { sM[tid] = -1e30f; sL[tid] = 0.0f; }

    float o[4][4] = {};

    for (int kt = 0; kt < S_ / 64; kt++) {
        __syncthreads();   // protect sK/sV/sS from previous iteration's readers
        // Load K, V tiles (contiguous) and mask slice
        {
            const float4* srcK = (const float4*)(Kh + (size_t)kt * 64 * DK_);
            const float4* srcV = (const float4*)(Vh + (size_t)kt * 64 * DK_);
            float4* dK = (float4*)sK;
            float4* dV = (float4*)sV;
            #pragma unroll
            for (int i = 0; i < 4; i++) {
                dK[tid + 256 * i] = srcK[tid + 256 * i];
                dV[tid + 256 * i] = srcV[tid + 256 * i];
            }
        }
        if (tid < 64) sMask[tid] = mask[(size_t)b * S_ + kt * 64 + tid];
        __syncthreads();

        // Scores: acc[i][j] = Q[q0+ty*4+i] . K[kt*64+tx*4+j]
        float acc[4][4] = {};
        #pragma unroll 8
        for (int kk = 0; kk < 64; kk++) {
            float a0 = sQ[(ty * 4 + 0) * 64 + kk];
            float a1 = sQ[(ty * 4 + 1) * 64 + kk];
            float a2 = sQ[(ty * 4 + 2) * 64 + kk];
            float a3 = sQ[(ty * 4 + 3) * 64 + kk];
            float b0 = sK[(tx * 4 + 0) * 64 + kk];
            float b1 = sK[(tx * 4 + 1) * 64 + kk];
            float b2 = sK[(tx * 4 + 2) * 64 + kk];
            float b3 = sK[(tx * 4 + 3) * 64 + kk];
            acc[0][0] += a0 * b0; acc[0][1] += a0 * b1; acc[0][2] += a0 * b2; acc[0][3] += a0 * b3;
            acc[1][0] += a1 * b0; acc[1][1] += a1 * b1; acc[1][2] += a1 * b2; acc[1][3] += a1 * b3;
            acc[2][0] += a2 * b0; acc[2][1] += a2 * b1; acc[2][2] += a2 * b2; acc[2][3] += a2 * b3;
            acc[3][0] += a3 * b0; acc[3][1] += a3 * b1; acc[3][2] += a3 * b2; acc[3][3] += a3 * b3;
        }

        // Scale + mask -> sS
        #pragma unroll
        for (int i = 0; i < 4; i++) {
            #pragma unroll
            for (int j = 0; j < 4; j++) {
                const int kc = tx * 4 + j;
                const float v = sMask[kc] ? acc[i][j] * 0.125f : -1e9f;
                sS[(ty * 4 + i) * 65 + kc] = v;
            }
        }
        __syncthreads();

        // Row-wise online softmax update (one thread per query row)
        if (tid < 64) {
            const int rr = tid;
            float mo = sM[rr];
            float mt = mo;
            #pragma unroll 8
            for (int c = 0; c < 64; c++) mt = fmaxf(mt, sS[rr * 65 + c]);
            const float corr = __expf(mo - mt);
            float lsum = 0.0f;
            #pragma unroll 8
            for (int c = 0; c < 64; c++) {
                const float p = __expf(sS[rr * 65 + c] - mt);
                sS[rr * 65 + c] = p;
                lsum += p;
            }
            sM[rr] = mt;
            sL[rr] = sL[rr] * corr + lsum;
            sC[rr] = corr;
        }
        __syncthreads();

        // Rescale accumulator and accumulate P @ V
        #pragma unroll
        for (int i = 0; i < 4; i++) {
            const float ci = sC[ty * 4 + i];
            o[i][0] *= ci; o[i][1] *= ci; o[i][2] *= ci; o[i][3] *= ci;
        }
        #pragma unroll 8
        for (int kk = 0; kk < 64; kk++) {
            float p0 = sS[(ty * 4 + 0) * 65 + kk];
            float p1 = sS[(ty * 4 + 1) * 65 + kk];
            float p2 = sS[(ty * 4 + 2) * 65 + kk];
            float p3 = sS[(ty * 4 + 3) * 65 + kk];
            float v0 = sV[kk * 64 + tx * 4 + 0];
            float v1 = sV[kk * 64 + tx * 4 + 1];
            float v2 = sV[kk * 64 + tx * 4 + 2];
            float v3 = sV[kk * 64 + tx * 4 + 3];
            o[0][0] += p0 * v0; o[0][1] += p0 * v1; o[0][2] += p0 * v2; o[0][3] += p0 * v3;
            o[1][0] += p1 * v0; o[1][1] += p1 * v1; o[1][2] += p1 * v2; o[1][3] += p1 * v3;
            o[2][0] += p2 * v0; o[2][1] += p2 * v1; o[2][2] += p2 * v2; o[2][3] += p2 * v3;
            o[3][0] += p3 * v0; o[3][1] += p3 * v1; o[3][2] += p3 * v2; o[3][3] += p3 * v3;
        }
    }
    __syncthreads();

    // Finalize: divide by l, write merged-head layout (B, S, H*DK)
    #pragma unroll
    for (int i = 0; i < 4; i++) {
        const int q = q0 + ty * 4 + i;
        const float inv_l = 1.0f / sL[ty * 4 + i];
        #pragma unroll
        for (int j = 0; j < 4; j++) {
            const int d = tx * 4 + j;
            gx[((size_t)b * S_ + q) * D_ + h * DK_ + d] = o[i][j] * inv_l;
        }
    }
}

// ---------------------------------------------------------------------------
// Launch
// ---------------------------------------------------------------------------
extern "C" void kernel_launch(void* const* d_in, const int* in_sizes, int n_in,
                              void* d_out, int out_size)
{
    const float* query = (const float*)d_in[0];
    const float* key_  = (const float*)d_in[1];
    const float* value = (const float*)d_in[2];
    const int*   mask  = (const int*)d_in[3];
    const float* Wq = (const float*)d_in[4];
    const float* bq = (const float*)d_in[5];
    const float* Wk = (const float*)d_in[6];
    const float* bk = (const float*)d_in[7];
    const float* Wv = (const float*)d_in[8];
    const float* bv = (const float*)d_in[9];
    const float* Wo = (const float*)d_in[10];
    const float* bo = (const float*)d_in[11];
    float* out = (float*)d_out;

    float *gq, *gk, *gv, *gx;
    cudaGetSymbolAddress((void**)&gq, g_q);
    cudaGetSymbolAddress((void**)&gk, g_k);
    cudaGetSymbolAddress((void**)&gv, g_v);
    cudaGetSymbolAddress((void**)&gx, g_x);

    cudaFuncSetAttribute(attn_kernel, cudaFuncAttributeMaxDynamicSharedMemorySize,
                         ATTN_SMEM_BYTES);

    dim3 gGemm(D_ / 64, M_TOT / 64);  // (12, 128)

    // QKV projections with head-split scatter
    gemm_kernel<<<gGemm, 256>>>(query, Wq, bq, gq, 1);
    gemm_kernel<<<gGemm, 256>>>(key_,  Wk, bk, gk, 1);
    gemm_kernel<<<gGemm, 256>>>(value, Wv, bv, gv, 1);

    // Attention
    dim3 gAttn(S_ / 64, H_, B_);      // (32, 12, 4)
    attn_kernel<<<gAttn, 256, ATTN_SMEM_BYTES>>>(gq, gk, gv, mask, gx);

    // Output projection (plain row-major epilogue)
    gemm_kernel<<<gGemm, 256>>>(gx, Wo, bo, out, 0);
}

// round 3
// speedup vs baseline: 2.4369x; 2.4369x over previous
#include <cuda_runtime.h>

#define B_  4
#define S_  2048
#define D_  768
#define H_  12
#define DK_ 64

typedef unsigned long long u64;

__device__ __forceinline__ u64 fma2(u64 a, u64 b, u64 c) {
    u64 d; asm("fma.rn.f32x2 %0,%1,%2,%3;" : "=l"(d) : "l"(a), "l"(b), "l"(c)); return d;
}
__device__ __forceinline__ u64 mul2(u64 a, u64 b) {
    u64 d; asm("mul.rn.f32x2 %0,%1,%2;" : "=l"(d) : "l"(a), "l"(b)); return d;
}
__device__ __forceinline__ u64 pack2(float x, float y) {
    u64 r; asm("mov.b64 %0,{%1,%2};" : "=l"(r) : "f"(x), "f"(y)); return r;
}
__device__ __forceinline__ float2 unpack2(u64 v) {
    float2 r; asm("mov.b64 {%0,%1},%2;" : "=f"(r.x), "=f"(r.y) : "l"(v)); return r;
}

__device__ float g_q[(size_t)B_ * H_ * S_ * DK_];
__device__ float g_k[(size_t)B_ * H_ * S_ * DK_];
__device__ float g_v[(size_t)B_ * H_ * S_ * DK_];
__device__ float g_x[(size_t)B_ * S_ * D_];

__global__ __launch_bounds__(256, 2) void gemm_kernel(
    const float* __restrict__ X, const float* __restrict__ W,
    const float* __restrict__ bias, float* __restrict__ out, int scatter)
{
    __shared__ float sXt[16 * 132];
    __shared__ float sW [128 * 20];

    const int tid = threadIdx.x;
    const int tx = tid & 15;
    const int ty = tid >> 4;
    const int m0 = blockIdx.y * 128;
    const int n0 = blockIdx.x * 128;

    u64 acc[4][8];
    #pragma unroll
    for (int p = 0; p < 4; p++)
        #pragma unroll
        for (int j = 0; j < 8; j++) acc[p][j] = 0ULL;

    for (int k0 = 0; k0 < D_; k0 += 16) {
        __syncthreads();
        #pragma unroll
        for (int i = 0; i < 2; i++) {
            int idx = tid + 256 * i;
            int m = idx >> 2, c4 = idx & 3;
            float4 xv = *(const float4*)(X + (size_t)(m0 + m) * D_ + k0 + c4 * 4);
            sXt[(c4 * 4 + 0) * 132 + m] = xv.x;
            sXt[(c4 * 4 + 1) * 132 + m] = xv.y;
            sXt[(c4 * 4 + 2) * 132 + m] = xv.z;
            sXt[(c4 * 4 + 3) * 132 + m] = xv.w;
        }
        #pragma unroll
        for (int i = 0; i < 2; i++) {
            int idx = tid + 256 * i;
            int n = idx >> 2, c4 = idx & 3;
            float4 wv = *(const float4*)(W + (size_t)(n0 + n) * D_ + k0 + c4 * 4);
            *(float4*)(sW + n * 20 + c4 * 4) = wv;
        }
        __syncthreads();

        #pragma unroll
        for (int kk = 0; kk < 16; kk++) {
            ulonglong2 a01 = *(const ulonglong2*)(sXt + kk * 132 + ty * 8);
            ulonglong2 a23 = *(const ulonglong2*)(sXt + kk * 132 + ty * 8 + 4);
            u64 ap0 = a01.x, ap1 = a01.y, ap2 = a23.x, ap3 = a23.y;
            #pragma unroll
            for (int j = 0; j < 8; j++) {
                float bv = sW[(tx + 16 * j) * 20 + kk];
                u64 br = pack2(bv, bv);
                acc[0][j] = fma2(ap0, br, acc[0][j]);
                acc[1][j] = fma2(ap1, br, acc[1][j]);
                acc[2][j] = fma2(ap2, br, acc[2][j]);
                acc[3][j] = fma2(ap3, br, acc[3][j]);
            }
        }
    }

    #pragma unroll
    for (int j = 0; j < 8; j++) {
        const int n = n0 + tx + 16 * j;
        const float bb = bias[n];
        #pragma unroll
        for (int p = 0; p < 4; p++) {
            float2 v = unpack2(acc[p][j]);
            const int m = m0 + ty * 8 + 2 * p;
            const float r0 = v.x + bb, r1 = v.y + bb;
            if (scatter) {
                const int h  = n >> 6, dk = n & 63;
                const int b0i = m >> 11,       s0i = m & 2047;
                const int b1i = (m + 1) >> 11, s1i = (m + 1) & 2047;
                out[((((size_t)b0i * H_ + h) * S_) + s0i) * DK_ + dk] = r0;
                out[((((size_t)b1i * H_ + h) * S_) + s1i) * DK_ + dk] = r1;
            } else {
                out[(size_t)m * D_ + n]       = r0;
                out[(size_t)(m + 1) * D_ + n] = r1;
            }
        }
    }
}

#define SQT_F (64 * 132)
#define SK_F  (64 * 68)
#define ATTN_SMEM_FLOATS (SQT_F + SK_F + SK_F + SQT_F)
#define ATTN_SMEM_BYTES  (ATTN_SMEM_FLOATS * 4)

__global__ __launch_bounds__(256, 2) void attn_kernel(
    const float* __restrict__ gq, const float* __restrict__ gk,
    const float* __restrict__ gv, const int* __restrict__ mask,
    float* __restrict__ gx)
{
    extern __shared__ float sm[];
    float* sQt = sm;
    float* sK  = sm + SQT_F;
    float* sV  = sK + SK_F;
    float* sPt = sV + SK_F;

    const int tid = threadIdx.x;
    const int tx = tid & 15;
    const int ty = tid >> 4;
    const int q0 = blockIdx.x * 128;
    const int h  = blockIdx.y;
    const int b  = blockIdx.z;

    const size_t hb = (((size_t)b * H_ + h) * S_) * DK_;
    const float* Qh = gq + hb;
    const float* Kh = gk + hb;
    const float* Vh = gv + hb;
    const int* mrow = mask + (size_t)b * S_;

    #pragma unroll
    for (int i = 0; i < 8; i++) {
        int idx = tid + 256 * i;
        int r = idx >> 4, c4 = idx & 15;
        float4 qv = *(const float4*)(Qh + (size_t)(q0 + r) * DK_ + c4 * 4);
        sQt[(c4 * 4 + 0) * 132 + r] = qv.x;
        sQt[(c4 * 4 + 1) * 132 + r] = qv.y;
        sQt[(c4 * 4 + 2) * 132 + r] = qv.z;
        sQt[(c4 * 4 + 3) * 132 + r] = qv.w;
    }

    float m_run[8], l_run[8];
    #pragma unroll
    for (int i = 0; i < 8; i++) { m_run[i] = -1e30f; l_run[i] = 0.0f; }
    u64 o2[4][4];
    #pragma unroll
    for (int p = 0; p < 4; p++)
        #pragma unroll
        for (int j = 0; j < 4; j++) o2[p][j] = 0ULL;

    for (int kt = 0; kt < S_ / 64; kt++) {
        __syncthreads();
        #pragma unroll
        for (int i = 0; i < 4; i++) {
            int idx = tid + 256 * i;
            int r = idx >> 4, c4 = idx & 15;
            *(float4*)(sK + r * 68 + c4 * 4) =
                *(const float4*)(Kh + (size_t)(kt * 64 + r) * DK_ + c4 * 4);
            *(float4*)(sV + r * 68 + c4 * 4) =
                *(const float4*)(Vh + (size_t)(kt * 64 + r) * DK_ + c4 * 4);
        }
        __syncthreads();

        u64 acc[4][4];
        #pragma unroll
        for (int p = 0; p < 4; p++)
            #pragma unroll
            for (int j = 0; j < 4; j++) acc[p][j] = 0ULL;

        #pragma unroll 8
        for (int kk = 0; kk < 64; kk++) {
            ulonglong2 a01 = *(const ulonglong2*)(sQt + kk * 132 + ty * 8);
            ulonglong2 a23 = *(const ulonglong2*)(sQt + kk * 132 + ty * 8 + 4);
            u64 ap0 = a01.x, ap1 = a01.y, ap2 = a23.x, ap3 = a23.y;
            #pragma unroll
            for (int j = 0; j < 4; j++) {
                float bv = sK[(tx + 16 * j) * 68 + kk];
                u64 br = pack2(bv, bv);
                acc[0][j] = fma2(ap0, br, acc[0][j]);
                acc[1][j] = fma2(ap1, br, acc[1][j]);
                acc[2][j] = fma2(ap2, br, acc[2][j]);
                acc[3][j] = fma2(ap3, br, acc[3][j]);
            }
        }

        int mk[4];
        #pragma unroll
        for (int j = 0; j < 4; j++) mk[j] = __ldg(mrow + kt * 64 + tx + 16 * j);

        #pragma unroll
        for (int p = 0; p < 4; p++) {
            float s0[4], s1[4];
            #pragma unroll
            for (int j = 0; j < 4; j++) {
                float2 u = unpack2(acc[p][j]);
                s0[j] = mk[j] ? u.x * 0.125f : -1e9f;
                s1[j] = mk[j] ? u.y * 0.125f : -1e9f;
            }
            float mx0 = fmaxf(fmaxf(s0[0], s0[1]), fmaxf(s0[2], s0[3]));
            float mx1 = fmaxf(fmaxf(s1[0], s1[1]), fmaxf(s1[2], s1[3]));
            #pragma unroll
            for (int d = 1; d < 16; d <<= 1) {
                mx0 = fmaxf(mx0, __shfl_xor_sync(0xffffffffu, mx0, d));
                mx1 = fmaxf(mx1, __shfl_xor_sync(0xffffffffu, mx1, d));
            }
            const int i0 = 2 * p, i1 = 2 * p + 1;
            float mn0 = fmaxf(m_run[i0], mx0);
            float mn1 = fmaxf(m_run[i1], mx1);
            float c0 = __expf(m_run[i0] - mn0);
            float c1 = __expf(m_run[i1] - mn1);
            float ps0 = 0.0f, ps1 = 0.0f;
            #pragma unroll
            for (int j = 0; j < 4; j++) {
                float e0 = __expf(s0[j] - mn0);
                float e1 = __expf(s1[j] - mn1);
                sPt[(tx + 16 * j) * 132 + ty * 8 + i0] = e0;
                sPt[(tx + 16 * j) * 132 + ty * 8 + i1] = e1;
                ps0 += e0; ps1 += e1;
            }
            #pragma unroll
            for (int d = 1; d < 16; d <<= 1) {
                ps0 += __shfl_xor_sync(0xffffffffu, ps0, d);
                ps1 += __shfl_xor_sync(0xffffffffu, ps1, d);
            }
            l_run[i0] = l_run[i0] * c0 + ps0;
            l_run[i1] = l_run[i1] * c1 + ps1;
            m_run[i0] = mn0;
            m_run[i1] = mn1;
            u64 c2 = pack2(c0, c1);
            #pragma unroll
            for (int j = 0; j < 4; j++) o2[p][j] = mul2(o2[p][j], c2);
        }
        __syncthreads();

        #pragma unroll 8
        for (int kk = 0; kk < 64; kk++) {
            ulonglong2 a01 = *(const ulonglong2*)(sPt + kk * 132 + ty * 8);
            ulonglong2 a23 = *(const ulonglong2*)(sPt + kk * 132 + ty * 8 + 4);
            u64 ap0 = a01.x, ap1 = a01.y, ap2 = a23.x, ap3 = a23.y;
            #pragma unroll
            for (int j = 0; j < 4; j++) {
                float vv = sV[kk * 68 + tx + 16 * j];
                u64 vr = pack2(vv, vv);
                o2[0][j] = fma2(ap0, vr, o2[0][j]);
                o2[1][j] = fma2(ap1, vr, o2[1][j]);
                o2[2][j] = fma2(ap2, vr, o2[2][j]);
                o2[3][j] = fma2(ap3, vr, o2[3][j]);
            }
        }
    }

    #pragma unroll
    for (int p = 0; p < 4; p++) {
        const float inv0 = 1.0f / l_run[2 * p];
        const float inv1 = 1.0f / l_run[2 * p + 1];
        const int q = q0 + ty * 8 + 2 * p;
        #pragma unroll
        for (int j = 0; j < 4; j++) {
            float2 v = unpack2(o2[p][j]);
            const int d = tx + 16 * j;
            gx[((size_t)b * S_ + q)     * D_ + h * DK_ + d] = v.x * inv0;
            gx[((size_t)b * S_ + q + 1) * D_ + h * DK_ + d] = v.y * inv1;
        }
    }
}

extern "C" void kernel_launch(void* const* d_in, const int* in_sizes, int n_in,
                              void* d_out, int out_size)
{
    const float* query = (const float*)d_in[0];
    const float* key_  = (const float*)d_in[1];
    const float* value = (const float*)d_in[2];
    const int*   mask  = (const int*)d_in[3];
    const float* Wq = (const float*)d_in[4];
    const float* bq = (const float*)d_in[5];
    const float* Wk = (const float*)d_in[6];
    const float* bk = (const float*)d_in[7];
    const float* Wv = (const float*)d_in[8];
    const float* bv = (const float*)d_in[9];
    const float* Wo = (const float*)d_in[10];
    const float* bo = (const float*)d_in[11];
    float* out = (float*)d_out;

    float *gq, *gk, *gv, *gx;
    cudaGetSymbolAddress((void**)&gq, g_q);
    cudaGetSymbolAddress((void**)&gk, g_k);
    cudaGetSymbolAddress((void**)&gv, g_v);
    cudaGetSymbolAddress((void**)&gx, g_x);

    cudaFuncSetAttribute(attn_kernel, cudaFuncAttributeMaxDynamicSharedMemorySize,
                         ATTN_SMEM_BYTES);

    dim3 gProj(D_ / 128, (B_ * S_) / 128);   // (6, 64)
    gemm_kernel<<<gProj, 256>>>(query, Wq, bq, gq, 1);
    gemm_kernel<<<gProj, 256>>>(key_,  Wk, bk, gk, 1);
    gemm_kernel<<<gProj, 256>>>(value, Wv, bv, gv, 1);

    dim3 gAttn(S_ / 128, H_, B_);            // (16, 12, 4)
    attn_kernel<<<gAttn, 256, ATTN_SMEM_BYTES>>>(gq, gk, gv, mask, gx);

    gemm_kernel<<<gProj, 256>>>(gx, Wo, bo, out, 0);
}

// round 7
// speedup vs baseline: 2.8351x; 1.1634x over previous
#include <cuda_runtime.h>
#include <cstdint>

#define B_  4
#define S_  2048
#define D_  768
#define H_  12
#define DK_ 64

typedef unsigned long long u64;

// ---- packed f32x2 helpers ----
__device__ __forceinline__ u64 fma2(u64 a, u64 b, u64 c) {
    u64 d; asm("fma.rn.f32x2 %0,%1,%2,%3;" : "=l"(d) : "l"(a), "l"(b), "l"(c)); return d;
}
__device__ __forceinline__ u64 mul2(u64 a, u64 b) {
    u64 d; asm("mul.rn.f32x2 %0,%1,%2;" : "=l"(d) : "l"(a), "l"(b)); return d;
}
__device__ __forceinline__ u64 pack2(float x, float y) {
    u64 r; asm("mov.b64 %0,{%1,%2};" : "=l"(r) : "f"(x), "f"(y)); return r;
}
__device__ __forceinline__ float2 unpack2(u64 v) {
    float2 r; asm("mov.b64 {%0,%1},%2;" : "=f"(r.x), "=f"(r.y) : "l"(v)); return r;
}

__device__ __forceinline__ uint32_t smem_u32(const void* p) {
    uint32_t a; asm("{ .reg .u64 t; cvta.to.shared.u64 t, %1; cvt.u32.u64 %0, t; }" : "=r"(a) : "l"(p));
    return a;
}
__device__ __forceinline__ void cp_async16(uint32_t dst, const void* src) {
    asm volatile("cp.async.cg.shared.global [%0], [%1], 16;" :: "r"(dst), "l"(src) : "memory");
}
#define CP_COMMIT() asm volatile("cp.async.commit_group;" ::: "memory")
#define CP_WAIT(n)  asm volatile("cp.async.wait_group %0;" :: "n"(n) : "memory")

// m16n8k8 tf32 mma
__device__ __forceinline__ void mma_tf32(float* c, const uint32_t* a, uint32_t b0, uint32_t b1) {
    asm volatile(
        "mma.sync.aligned.m16n8k8.row.col.f32.tf32.tf32.f32 "
        "{%0,%1,%2,%3}, {%4,%5,%6,%7}, {%8,%9}, {%0,%1,%2,%3};"
        : "+f"(c[0]), "+f"(c[1]), "+f"(c[2]), "+f"(c[3])
        : "r"(a[0]), "r"(a[1]), "r"(a[2]), "r"(a[3]), "r"(b0), "r"(b1));
}

// 3xTF32 split: hi = top bits (exactly tf32), lo = x - hi (exact fp32)
__device__ __forceinline__ void split_tf32(float x, uint32_t& hi, uint32_t& lo) {
    uint32_t xb = __float_as_uint(x);
    hi = xb & 0xFFFFE000u;
    lo = __float_as_uint(x - __uint_as_float(hi));
}

// Scratch
__device__ float g_q[(size_t)B_ * H_ * S_ * DK_];
__device__ float g_k[(size_t)B_ * H_ * S_ * DK_];
__device__ float g_v[(size_t)B_ * H_ * S_ * DK_];
__device__ float g_x[(size_t)B_ * S_ * D_];

// ---------------------------------------------------------------------------
// mma.sync 3xTF32 GEMM: Y[m,n] = X[m,:].W[n,:] + bias[n].
// CTA 128x128, 8 warps (4Mx2N), warp tile 32x64. K chunks of 32,
// cp.async double-buffered. A*B = Ah*Bh + Ah*Bl + Al*Bh (fp32-accurate).
// ---------------------------------------------------------------------------
#define GK_PITCH 36
#define GK_MATF  (128 * GK_PITCH)
#define GK_MATB  (GK_MATF * 4)
#define GK_STAGEF (2 * GK_MATF)
#define GK_STAGEB (2 * GK_MATB)
#define GK_SMEM  (2 * GK_STAGEB)             // 73728 bytes

__global__ __launch_bounds__(256, 2) void gemm_mma(
    const float* __restrict__ X, const float* __restrict__ W,
    const float* __restrict__ bias, float* __restrict__ out, int scatter)
{
    extern __shared__ float smf[];
    const uint32_t sbase = smem_u32(smf);
    const int tid = threadIdx.x;
    const int lane = tid & 31;
    const int wid = tid >> 5;
    const int wm = (wid & 3) * 32;
    const int wn = (wid >> 2) * 64;
    const int m0 = blockIdx.y * 128;
    const int n0 = blockIdx.x * 128;
    const int g = lane >> 2, t = lane & 3;

    float c[2][8][4];
    #pragma unroll
    for (int mi = 0; mi < 2; mi++)
        #pragma unroll
        for (int nj = 0; nj < 8; nj++)
            #pragma unroll
            for (int q = 0; q < 4; q++) c[mi][nj][q] = 0.0f;

    auto issue = [&](int ch) {
        const int k0 = ch * 32;
        const uint32_t dstA = sbase + (ch & 1) * GK_STAGEB;
        const uint32_t dstB = dstA + GK_MATB;
        #pragma unroll
        for (int i = 0; i < 4; i++) {
            int idx = tid + 256 * i;
            int r = idx >> 3, c4 = idx & 7;
            cp_async16(dstA + r * (GK_PITCH * 4) + c4 * 16,
                       X + (size_t)(m0 + r) * D_ + k0 + c4 * 4);
            cp_async16(dstB + r * (GK_PITCH * 4) + c4 * 16,
                       W + (size_t)(n0 + r) * D_ + k0 + c4 * 4);
        }
        CP_COMMIT();
    };

    issue(0);
    for (int ch = 0; ch < 24; ch++) {
        if (ch + 1 < 24) { issue(ch + 1); CP_WAIT(1); }
        else             { CP_WAIT(0); }
        __syncthreads();

        const float* sA = smf + (ch & 1) * GK_STAGEF;
        const float* sB = sA + GK_MATF;

        #pragma unroll
        for (int k8 = 0; k8 < 4; k8++) {
            const int kb = k8 * 8;
            uint32_t ah[2][4], al[2][4];
            #pragma unroll
            for (int mi = 0; mi < 2; mi++) {
                const int r0 = wm + mi * 16 + g;
                split_tf32(sA[(r0    ) * GK_PITCH + kb + t    ], ah[mi][0], al[mi][0]);
                split_tf32(sA[(r0 + 8) * GK_PITCH + kb + t    ], ah[mi][1], al[mi][1]);
                split_tf32(sA[(r0    ) * GK_PITCH + kb + t + 4], ah[mi][2], al[mi][2]);
                split_tf32(sA[(r0 + 8) * GK_PITCH + kb + t + 4], ah[mi][3], al[mi][3]);
            }
            #pragma unroll
            for (int nj = 0; nj < 8; nj++) {
                const int cn = wn + nj * 8 + g;
                uint32_t bh0, bl0, bh1, bl1;
                split_tf32(sB[cn * GK_PITCH + kb + t    ], bh0, bl0);
                split_tf32(sB[cn * GK_PITCH + kb + t + 4], bh1, bl1);
                // hi*hi + hi*lo + lo*hi
                mma_tf32(c[0][nj], ah[0], bh0, bh1);
                mma_tf32(c[0][nj], ah[0], bl0, bl1);
                mma_tf32(c[0][nj], al[0], bh0, bh1);
                mma_tf32(c[1][nj], ah[1], bh0, bh1);
                mma_tf32(c[1][nj], ah[1], bl0, bl1);
                mma_tf32(c[1][nj], al[1], bh0, bh1);
            }
        }
        __syncthreads();
    }

    #pragma unroll
    for (int nj = 0; nj < 8; nj++) {
        const int n = n0 + wn + nj * 8 + 2 * t;
        const float2 bb = *(const float2*)(bias + n);
        #pragma unroll
        for (int mi = 0; mi < 2; mi++) {
            #pragma unroll
            for (int half = 0; half < 2; half++) {
                const int m = m0 + wm + mi * 16 + g + 8 * half;
                float2 v;
                v.x = c[mi][nj][2 * half + 0] + bb.x;
                v.y = c[mi][nj][2 * half + 1] + bb.y;
                if (scatter) {
                    const int h = n >> 6, dk = n & 63;
                    const int bi = m >> 11, s = m & 2047;
                    *(float2*)(out + ((((size_t)bi * H_ + h) * S_) + s) * DK_ + dk) = v;
                } else {
                    *(float2*)(out + (size_t)m * D_ + n) = v;
                }
            }
        }
    }
}

// ---------------------------------------------------------------------------
// Flash attention (f32x2 CUDA-core version, unchanged — known good)
// ---------------------------------------------------------------------------
#define SQT_F (64 * 132)
#define SK_F  (64 * 68)
#define ATTN_SMEM_FLOATS (SQT_F + SK_F + SK_F + SQT_F)
#define ATTN_SMEM_BYTES  (ATTN_SMEM_FLOATS * 4)

__global__ __launch_bounds__(256, 2) void attn_kernel(
    const float* __restrict__ gq, const float* __restrict__ gk,
    const float* __restrict__ gv, const int* __restrict__ mask,
    float* __restrict__ gx)
{
    extern __shared__ float sm[];
    float* sQt = sm;
    float* sK  = sm + SQT_F;
    float* sV  = sK + SK_F;
    float* sPt = sV + SK_F;

    const int tid = threadIdx.x;
    const int tx = tid & 15;
    const int ty = tid >> 4;
    const int q0 = blockIdx.x * 128;
    const int h  = blockIdx.y;
    const int b  = blockIdx.z;

    const size_t hb = (((size_t)b * H_ + h) * S_) * DK_;
    const float* Qh = gq + hb;
    const float* Kh = gk + hb;
    const float* Vh = gv + hb;
    const int* mrow = mask + (size_t)b * S_;

    #pragma unroll
    for (int i = 0; i < 8; i++) {
        int idx = tid + 256 * i;
        int r = idx >> 4, c4 = idx & 15;
        float4 qv = *(const float4*)(Qh + (size_t)(q0 + r) * DK_ + c4 * 4);
        sQt[(c4 * 4 + 0) * 132 + r] = qv.x;
        sQt[(c4 * 4 + 1) * 132 + r] = qv.y;
        sQt[(c4 * 4 + 2) * 132 + r] = qv.z;
        sQt[(c4 * 4 + 3) * 132 + r] = qv.w;
    }

    float m_run[8], l_run[8];
    #pragma unroll
    for (int i = 0; i < 8; i++) { m_run[i] = -1e30f; l_run[i] = 0.0f; }
    u64 o2[4][4];
    #pragma unroll
    for (int p = 0; p < 4; p++)
        #pragma unroll
        for (int j = 0; j < 4; j++) o2[p][j] = 0ULL;

    for (int kt = 0; kt < S_ / 64; kt++) {
        __syncthreads();
        #pragma unroll
        for (int i = 0; i < 4; i++) {
            int idx = tid + 256 * i;
            int r = idx >> 4, c4 = idx & 15;
            *(float4*)(sK + r * 68 + c4 * 4) =
                *(const float4*)(Kh + (size_t)(kt * 64 + r) * DK_ + c4 * 4);
            *(float4*)(sV + r * 68 + c4 * 4) =
                *(const float4*)(Vh + (size_t)(kt * 64 + r) * DK_ + c4 * 4);
        }
        __syncthreads();

        u64 acc[4][4];
        #pragma unroll
        for (int p = 0; p < 4; p++)
            #pragma unroll
            for (int j = 0; j < 4; j++) acc[p][j] = 0ULL;

        #pragma unroll 8
        for (int kk = 0; kk < 64; kk++) {
            ulonglong2 a01 = *(const ulonglong2*)(sQt + kk * 132 + ty * 8);
            ulonglong2 a23 = *(const ulonglong2*)(sQt + kk * 132 + ty * 8 + 4);
            u64 ap0 = a01.x, ap1 = a01.y, ap2 = a23.x, ap3 = a23.y;
            #pragma unroll
            for (int j = 0; j < 4; j++) {
                float bv = sK[(tx + 16 * j) * 68 + kk];
                u64 br = pack2(bv, bv);
                acc[0][j] = fma2(ap0, br, acc[0][j]);
                acc[1][j] = fma2(ap1, br, acc[1][j]);
                acc[2][j] = fma2(ap2, br, acc[2][j]);
                acc[3][j] = fma2(ap3, br, acc[3][j]);
            }
        }

        int mk[4];
        #pragma unroll
        for (int j = 0; j < 4; j++) mk[j] = __ldg(mrow + kt * 64 + tx + 16 * j);

        #pragma unroll
        for (int p = 0; p < 4; p++) {
            float s0[4], s1[4];
            #pragma unroll
            for (int j = 0; j < 4; j++) {
                float2 u = unpack2(acc[p][j]);
                s0[j] = mk[j] ? u.x * 0.125f : -1e9f;
                s1[j] = mk[j] ? u.y * 0.125f : -1e9f;
            }
            float mx0 = fmaxf(fmaxf(s0[0], s0[1]), fmaxf(s0[2], s0[3]));
            float mx1 = fmaxf(fmaxf(s1[0], s1[1]), fmaxf(s1[2], s1[3]));
            #pragma unroll
            for (int d = 1; d < 16; d <<= 1) {
                mx0 = fmaxf(mx0, __shfl_xor_sync(0xffffffffu, mx0, d));
                mx1 = fmaxf(mx1, __shfl_xor_sync(0xffffffffu, mx1, d));
            }
            const int i0 = 2 * p, i1 = 2 * p + 1;
            float mn0 = fmaxf(m_run[i0], mx0);
            float mn1 = fmaxf(m_run[i1], mx1);
            float c0 = __expf(m_run[i0] - mn0);
            float c1 = __expf(m_run[i1] - mn1);
            float ps0 = 0.0f, ps1 = 0.0f;
            #pragma unroll
            for (int j = 0; j < 4; j++) {
                float e0 = __expf(s0[j] - mn0);
                float e1 = __expf(s1[j] - mn1);
                sPt[(tx + 16 * j) * 132 + ty * 8 + i0] = e0;
                sPt[(tx + 16 * j) * 132 + ty * 8 + i1] = e1;
                ps0 += e0; ps1 += e1;
            }
            #pragma unroll
            for (int d = 1; d < 16; d <<= 1) {
                ps0 += __shfl_xor_sync(0xffffffffu, ps0, d);
                ps1 += __shfl_xor_sync(0xffffffffu, ps1, d);
            }
            l_run[i0] = l_run[i0] * c0 + ps0;
            l_run[i1] = l_run[i1] * c1 + ps1;
            m_run[i0] = mn0;
            m_run[i1] = mn1;
            u64 c2 = pack2(c0, c1);
            #pragma unroll
            for (int j = 0; j < 4; j++) o2[p][j] = mul2(o2[p][j], c2);
        }
        __syncthreads();

        #pragma unroll 8
        for (int kk = 0; kk < 64; kk++) {
            ulonglong2 a01 = *(const ulonglong2*)(sPt + kk * 132 + ty * 8);
            ulonglong2 a23 = *(const ulonglong2*)(sPt + kk * 132 + ty * 8 + 4);
            u64 ap0 = a01.x, ap1 = a01.y, ap2 = a23.x, ap3 = a23.y;
            #pragma unroll
            for (int j = 0; j < 4; j++) {
                float vv = sV[kk * 68 + tx + 16 * j];
                u64 vr = pack2(vv, vv);
                o2[0][j] = fma2(ap0, vr, o2[0][j]);
                o2[1][j] = fma2(ap1, vr, o2[1][j]);
                o2[2][j] = fma2(ap2, vr, o2[2][j]);
                o2[3][j] = fma2(ap3, vr, o2[3][j]);
            }
        }
    }

    #pragma unroll
    for (int p = 0; p < 4; p++) {
        const float inv0 = 1.0f / l_run[2 * p];
        const float inv1 = 1.0f / l_run[2 * p + 1];
        const int q = q0 + ty * 8 + 2 * p;
        #pragma unroll
        for (int j = 0; j < 4; j++) {
            float2 v = unpack2(o2[p][j]);
            const int d = tx + 16 * j;
            gx[((size_t)b * S_ + q)     * D_ + h * DK_ + d] = v.x * inv0;
            gx[((size_t)b * S_ + q + 1) * D_ + h * DK_ + d] = v.y * inv1;
        }
    }
}

extern "C" void kernel_launch(void* const* d_in, const int* in_sizes, int n_in,
                              void* d_out, int out_size)
{
    const float* query = (const float*)d_in[0];
    const float* key_  = (const float*)d_in[1];
    const float* value = (const float*)d_in[2];
    const int*   mask  = (const int*)d_in[3];
    const float* Wq = (const float*)d_in[4];
    const float* bq = (const float*)d_in[5];
    const float* Wk = (const float*)d_in[6];
    const float* bk = (const float*)d_in[7];
    const float* Wv = (const float*)d_in[8];
    const float* bv = (const float*)d_in[9];
    const float* Wo = (const float*)d_in[10];
    const float* bo = (const float*)d_in[11];
    float* out = (float*)d_out;

    float *gq, *gk, *gv, *gx;
    cudaGetSymbolAddress((void**)&gq, g_q);
    cudaGetSymbolAddress((void**)&gk, g_k);
    cudaGetSymbolAddress((void**)&gv, g_v);
    cudaGetSymbolAddress((void**)&gx, g_x);

    cudaFuncSetAttribute(gemm_mma, cudaFuncAttributeMaxDynamicSharedMemorySize, GK_SMEM);
    cudaFuncSetAttribute(attn_kernel, cudaFuncAttributeMaxDynamicSharedMemorySize,
                         ATTN_SMEM_BYTES);

    dim3 gProj(D_ / 128, (B_ * S_) / 128);   // (6, 64)
    gemm_mma<<<gProj, 256, GK_SMEM>>>(query, Wq, bq, gq, 1);
    gemm_mma<<<gProj, 256, GK_SMEM>>>(key_,  Wk, bk, gk, 1);
    gemm_mma<<<gProj, 256, GK_SMEM>>>(value, Wv, bv, gv, 1);

    dim3 gAttn(S_ / 128, H_, B_);            // (16, 12, 4)
    attn_kernel<<<gAttn, 256, ATTN_SMEM_BYTES>>>(gq, gk, gv, mask, gx);

    gemm_mma<<<gProj, 256, GK_SMEM>>>(gx, Wo, bo, out, 0);
}

// round 8
// speedup vs baseline: 3.4614x; 1.2209x over previous
#include <cuda_runtime.h>
#include <cstdint>

#define B_  4
#define S_  2048
#define D_  768
#define H_  12
#define DK_ 64

__device__ __forceinline__ uint32_t smem_u32(const void* p) {
    uint32_t a; asm("{ .reg .u64 t; cvta.to.shared.u64 t, %1; cvt.u32.u64 %0, t; }" : "=r"(a) : "l"(p));
    return a;
}
__device__ __forceinline__ void cp_async16(uint32_t dst, const void* src) {
    asm volatile("cp.async.cg.shared.global [%0], [%1], 16;" :: "r"(dst), "l"(src) : "memory");
}
#define CP_COMMIT() asm volatile("cp.async.commit_group;" ::: "memory")
#define CP_WAIT(n)  asm volatile("cp.async.wait_group %0;" :: "n"(n) : "memory")

// m16n8k8 tf32 mma
__device__ __forceinline__ void mma_tf32(float* c, const uint32_t* a, uint32_t b0, uint32_t b1) {
    asm volatile(
        "mma.sync.aligned.m16n8k8.row.col.f32.tf32.tf32.f32 "
        "{%0,%1,%2,%3}, {%4,%5,%6,%7}, {%8,%9}, {%0,%1,%2,%3};"
        : "+f"(c[0]), "+f"(c[1]), "+f"(c[2]), "+f"(c[3])
        : "r"(a[0]), "r"(a[1]), "r"(a[2]), "r"(a[3]), "r"(b0), "r"(b1));
}
// 3xTF32 split: hi = top bits (exactly tf32), lo = x - hi (exact fp32)
__device__ __forceinline__ void split_tf32(float x, uint32_t& hi, uint32_t& lo) {
    uint32_t xb = __float_as_uint(x);
    hi = xb & 0xFFFFE000u;
    lo = __float_as_uint(x - __uint_as_float(hi));
}

// Scratch
__device__ float g_q[(size_t)B_ * H_ * S_ * DK_];
__device__ float g_k[(size_t)B_ * H_ * S_ * DK_];
__device__ float g_v[(size_t)B_ * H_ * S_ * DK_];
__device__ float g_x[(size_t)B_ * S_ * D_];

// ---------------------------------------------------------------------------
// mma.sync 3xTF32 GEMM (unchanged from R7 — passed at rel_err 2.5e-5)
// ---------------------------------------------------------------------------
#define GK_PITCH 36
#define GK_MATF  (128 * GK_PITCH)
#define GK_MATB  (GK_MATF * 4)
#define GK_STAGEF (2 * GK_MATF)
#define GK_STAGEB (2 * GK_MATB)
#define GK_SMEM  (2 * GK_STAGEB)

__global__ __launch_bounds__(256, 2) void gemm_mma(
    const float* __restrict__ X, const float* __restrict__ W,
    const float* __restrict__ bias, float* __restrict__ out, int scatter)
{
    extern __shared__ float smf[];
    const uint32_t sbase = smem_u32(smf);
    const int tid = threadIdx.x;
    const int lane = tid & 31;
    const int wid = tid >> 5;
    const int wm = (wid & 3) * 32;
    const int wn = (wid >> 2) * 64;
    const int m0 = blockIdx.y * 128;
    const int n0 = blockIdx.x * 128;
    const int g = lane >> 2, t = lane & 3;

    float c[2][8][4];
    #pragma unroll
    for (int mi = 0; mi < 2; mi++)
        #pragma unroll
        for (int nj = 0; nj < 8; nj++)
            #pragma unroll
            for (int q = 0; q < 4; q++) c[mi][nj][q] = 0.0f;

    auto issue = [&](int ch) {
        const int k0 = ch * 32;
        const uint32_t dstA = sbase + (ch & 1) * GK_STAGEB;
        const uint32_t dstB = dstA + GK_MATB;
        #pragma unroll
        for (int i = 0; i < 4; i++) {
            int idx = tid + 256 * i;
            int r = idx >> 3, c4 = idx & 7;
            cp_async16(dstA + r * (GK_PITCH * 4) + c4 * 16,
                       X + (size_t)(m0 + r) * D_ + k0 + c4 * 4);
            cp_async16(dstB + r * (GK_PITCH * 4) + c4 * 16,
                       W + (size_t)(n0 + r) * D_ + k0 + c4 * 4);
        }
        CP_COMMIT();
    };

    issue(0);
    for (int ch = 0; ch < 24; ch++) {
        if (ch + 1 < 24) { issue(ch + 1); CP_WAIT(1); }
        else             { CP_WAIT(0); }
        __syncthreads();

        const float* sA = smf + (ch & 1) * GK_STAGEF;
        const float* sB = sA + GK_MATF;

        #pragma unroll
        for (int k8 = 0; k8 < 4; k8++) {
            const int kb = k8 * 8;
            uint32_t ah[2][4], al[2][4];
            #pragma unroll
            for (int mi = 0; mi < 2; mi++) {
                const int r0 = wm + mi * 16 + g;
                split_tf32(sA[(r0    ) * GK_PITCH + kb + t    ], ah[mi][0], al[mi][0]);
                split_tf32(sA[(r0 + 8) * GK_PITCH + kb + t    ], ah[mi][1], al[mi][1]);
                split_tf32(sA[(r0    ) * GK_PITCH + kb + t + 4], ah[mi][2], al[mi][2]);
                split_tf32(sA[(r0 + 8) * GK_PITCH + kb + t + 4], ah[mi][3], al[mi][3]);
            }
            #pragma unroll
            for (int nj = 0; nj < 8; nj++) {
                const int cn = wn + nj * 8 + g;
                uint32_t bh0, bl0, bh1, bl1;
                split_tf32(sB[cn * GK_PITCH + kb + t    ], bh0, bl0);
                split_tf32(sB[cn * GK_PITCH + kb + t + 4], bh1, bl1);
                mma_tf32(c[0][nj], ah[0], bh0, bh1);
                mma_tf32(c[0][nj], ah[0], bl0, bl1);
                mma_tf32(c[0][nj], al[0], bh0, bh1);
                mma_tf32(c[1][nj], ah[1], bh0, bh1);
                mma_tf32(c[1][nj], ah[1], bl0, bl1);
                mma_tf32(c[1][nj], al[1], bh0, bh1);
            }
        }
        __syncthreads();
    }

    #pragma unroll
    for (int nj = 0; nj < 8; nj++) {
        const int n = n0 + wn + nj * 8 + 2 * t;
        const float2 bb = *(const float2*)(bias + n);
        #pragma unroll
        for (int mi = 0; mi < 2; mi++) {
            #pragma unroll
            for (int half = 0; half < 2; half++) {
                const int m = m0 + wm + mi * 16 + g + 8 * half;
                float2 v;
                v.x = c[mi][nj][2 * half + 0] + bb.x;
                v.y = c[mi][nj][2 * half + 1] + bb.y;
                if (scatter) {
                    const int h = n >> 6, dk = n & 63;
                    const int bi = m >> 11, s = m & 2047;
                    *(float2*)(out + ((((size_t)bi * H_ + h) * S_) + s) * DK_ + dk) = v;
                } else {
                    *(float2*)(out + (size_t)m * D_ + n) = v;
                }
            }
        }
    }
}

// ---------------------------------------------------------------------------
// Tensor-core flash attention: 128q x 64k tiles, 8 warps (16 q-rows each),
// 3xTF32 mma for QK^T and PV, register-prefetch K/V pipeline.
// Layouts: sQ/sK/sP pitch 68, sV pitch 72 (conflict-free fragment LDS).
// ---------------------------------------------------------------------------
#define AQ_OFF 0
#define AK_OFF 8704                       // 128*68
#define AV_OFF (AK_OFF + 64 * 68)         // 13056
#define AP_OFF (AV_OFF + 64 * 72)         // 17664
#define AM_OFF (AP_OFF + 128 * 68)        // 26368 (ints)
#define ATTN_SMEM_BYTES ((AM_OFF + 64) * 4)   // 105728

__global__ __launch_bounds__(256, 2) void attn_mma(
    const float* __restrict__ gq, const float* __restrict__ gk,
    const float* __restrict__ gv, const int* __restrict__ mask,
    float* __restrict__ gx)
{
    extern __shared__ float sm[];
    float* sQ = sm + AQ_OFF;
    float* sK = sm + AK_OFF;
    float* sV = sm + AV_OFF;
    float* sP = sm + AP_OFF;
    int*  sMk = (int*)(sm + AM_OFF);

    const int tid = threadIdx.x;
    const int wid = tid >> 5;
    const int lane = tid & 31;
    const int g = lane >> 2, t = lane & 3;
    const int q0 = blockIdx.x * 128;
    const int h  = blockIdx.y;
    const int b  = blockIdx.z;
    const int rowA = 16 * wid + g;

    const size_t hb = (((size_t)b * H_ + h) * S_) * DK_;
    const float* Qh = gq + hb;
    const float* Kh = gk + hb;
    const float* Vh = gv + hb;
    const int* mrow = mask + (size_t)b * S_;

    // Load Q (128x64), K0, V0, mask0
    #pragma unroll
    for (int i = 0; i < 8; i++) {
        int idx = tid + 256 * i, r = idx >> 4, c4 = idx & 15;
        *(float4*)(sQ + r * 68 + c4 * 4) = *(const float4*)(Qh + (size_t)(q0 + r) * DK_ + c4 * 4);
    }
    #pragma unroll
    for (int i = 0; i < 4; i++) {
        int idx = tid + 256 * i, r = idx >> 4, c4 = idx & 15;
        *(float4*)(sK + r * 68 + c4 * 4) = *(const float4*)(Kh + (size_t)r * DK_ + c4 * 4);
        *(float4*)(sV + r * 72 + c4 * 4) = *(const float4*)(Vh + (size_t)r * DK_ + c4 * 4);
    }
    if (tid < 64) sMk[tid] = mrow[tid];
    __syncthreads();

    float m0r = -1e30f, m1r = -1e30f, l0 = 0.0f, l1 = 0.0f;
    float co[8][4];
    #pragma unroll
    for (int nj = 0; nj < 8; nj++)
        #pragma unroll
        for (int q = 0; q < 4; q++) co[nj][q] = 0.0f;

    for (int kt = 0; kt < S_ / 64; kt++) {
        const int kn = (kt + 1 < S_ / 64) ? kt + 1 : 0;

        // prefetch next K tile into registers (hidden under QK compute)
        float4 pk[4];
        #pragma unroll
        for (int i = 0; i < 4; i++) {
            int idx = tid + 256 * i, r = idx >> 4, c4 = idx & 15;
            pk[i] = *(const float4*)(Kh + (size_t)(kn * 64 + r) * DK_ + c4 * 4);
        }

        // ---- QK^T (3xTF32): cs[nj] rows {rowA,rowA+8}, cols {8nj+2t,+1} ----
        float cs[8][4];
        #pragma unroll
        for (int nj = 0; nj < 8; nj++)
            #pragma unroll
            for (int q = 0; q < 4; q++) cs[nj][q] = 0.0f;

        #pragma unroll
        for (int ks = 0; ks < 8; ks++) {
            const int kb = ks * 8;
            uint32_t ah[4], al[4];
            split_tf32(sQ[(rowA    ) * 68 + kb + t    ], ah[0], al[0]);
            split_tf32(sQ[(rowA + 8) * 68 + kb + t    ], ah[1], al[1]);
            split_tf32(sQ[(rowA    ) * 68 + kb + t + 4], ah[2], al[2]);
            split_tf32(sQ[(rowA + 8) * 68 + kb + t + 4], ah[3], al[3]);
            #pragma unroll
            for (int nj = 0; nj < 8; nj++) {
                uint32_t bh0, bl0, bh1, bl1;
                split_tf32(sK[(g + 8 * nj) * 68 + kb + t    ], bh0, bl0);
                split_tf32(sK[(g + 8 * nj) * 68 + kb + t + 4], bh1, bl1);
                mma_tf32(cs[nj], ah, bh0, bh1);
                mma_tf32(cs[nj], ah, bl0, bl1);
                mma_tf32(cs[nj], al, bh0, bh1);
            }
        }

        // ---- mask + scale + online softmax (row stats in 4-lane groups) ----
        float mx0 = -1e30f, mx1 = -1e30f;
        #pragma unroll
        for (int nj = 0; nj < 8; nj++) {
            const int c0m = sMk[8 * nj + 2 * t];
            const int c1m = sMk[8 * nj + 2 * t + 1];
            cs[nj][0] = c0m ? cs[nj][0] * 0.125f : -1e9f;
            cs[nj][1] = c1m ? cs[nj][1] * 0.125f : -1e9f;
            cs[nj][2] = c0m ? cs[nj][2] * 0.125f : -1e9f;
            cs[nj][3] = c1m ? cs[nj][3] * 0.125f : -1e9f;
            mx0 = fmaxf(mx0, fmaxf(cs[nj][0], cs[nj][1]));
            mx1 = fmaxf(mx1, fmaxf(cs[nj][2], cs[nj][3]));
        }
        #pragma unroll
        for (int d = 1; d < 4; d <<= 1) {
            mx0 = fmaxf(mx0, __shfl_xor_sync(0xffffffffu, mx0, d));
            mx1 = fmaxf(mx1, __shfl_xor_sync(0xffffffffu, mx1, d));
        }
        const float mn0 = fmaxf(m0r, mx0);
        const float mn1 = fmaxf(m1r, mx1);
        const float cr0 = __expf(m0r - mn0);
        const float cr1 = __expf(m1r - mn1);
        #pragma unroll
        for (int nj = 0; nj < 8; nj++) {
            co[nj][0] *= cr0; co[nj][1] *= cr0;
            co[nj][2] *= cr1; co[nj][3] *= cr1;
        }
        float ps0 = 0.0f, ps1 = 0.0f;
        #pragma unroll
        for (int nj = 0; nj < 8; nj++) {
            float e0 = __expf(cs[nj][0] - mn0);
            float e1 = __expf(cs[nj][1] - mn0);
            float e2 = __expf(cs[nj][2] - mn1);
            float e3 = __expf(cs[nj][3] - mn1);
            float2 v0 = make_float2(e0, e1);
            float2 v1 = make_float2(e2, e3);
            *(float2*)(sP + (rowA    ) * 68 + 8 * nj + 2 * t) = v0;
            *(float2*)(sP + (rowA + 8) * 68 + 8 * nj + 2 * t) = v1;
            ps0 += e0 + e1; ps1 += e2 + e3;
        }
        #pragma unroll
        for (int d = 1; d < 4; d <<= 1) {
            ps0 += __shfl_xor_sync(0xffffffffu, ps0, d);
            ps1 += __shfl_xor_sync(0xffffffffu, ps1, d);
        }
        l0 = l0 * cr0 + ps0;
        l1 = l1 * cr1 + ps1;
        m0r = mn0; m1r = mn1;

        __syncthreads();   // all warps done reading sK/sMk; sP fully written

        // store prefetched K, load next mask, prefetch next V
        #pragma unroll
        for (int i = 0; i < 4; i++) {
            int idx = tid + 256 * i, r = idx >> 4, c4 = idx & 15;
            *(float4*)(sK + r * 68 + c4 * 4) = pk[i];
        }
        if (tid < 64) sMk[tid] = mrow[kn * 64 + tid];
        float4 pv[4];
        #pragma unroll
        for (int i = 0; i < 4; i++) {
            int idx = tid + 256 * i, r = idx >> 4, c4 = idx & 15;
            pv[i] = *(const float4*)(Vh + (size_t)(kn * 64 + r) * DK_ + c4 * 4);
        }

        // ---- PV (3xTF32): co[nj] += P(16x64) x V(64x64) ----
        #pragma unroll
        for (int ks = 0; ks < 8; ks++) {
            const int kb = ks * 8;
            uint32_t ah[4], al[4];
            split_tf32(sP[(rowA    ) * 68 + kb + t    ], ah[0], al[0]);
            split_tf32(sP[(rowA + 8) * 68 + kb + t    ], ah[1], al[1]);
            split_tf32(sP[(rowA    ) * 68 + kb + t + 4], ah[2], al[2]);
            split_tf32(sP[(rowA + 8) * 68 + kb + t + 4], ah[3], al[3]);
            #pragma unroll
            for (int nj = 0; nj < 8; nj++) {
                uint32_t bh0, bl0, bh1, bl1;
                split_tf32(sV[(kb + t    ) * 72 + 8 * nj + g], bh0, bl0);
                split_tf32(sV[(kb + t + 4) * 72 + 8 * nj + g], bh1, bl1);
                mma_tf32(co[nj], ah, bh0, bh1);
                mma_tf32(co[nj], ah, bl0, bl1);
                mma_tf32(co[nj], al, bh0, bh1);
            }
        }
        __syncthreads();   // all warps done reading sV (and sP)
        #pragma unroll
        for (int i = 0; i < 4; i++) {
            int idx = tid + 256 * i, r = idx >> 4, c4 = idx & 15;
            *(float4*)(sV + r * 72 + c4 * 4) = pv[i];
        }
    }

    // ---- finalize: /l, write merged-head layout (B,S,H*DK) ----
    const float inv0 = 1.0f / l0;
    const float inv1 = 1.0f / l1;
    #pragma unroll
    for (int nj = 0; nj < 8; nj++) {
        const int d = 8 * nj + 2 * t;
        float2 v0 = make_float2(co[nj][0] * inv0, co[nj][1] * inv0);
        float2 v1 = make_float2(co[nj][2] * inv1, co[nj][3] * inv1);
        *(float2*)(gx + ((size_t)b * S_ + q0 + rowA    ) * D_ + h * DK_ + d) = v0;
        *(float2*)(gx + ((size_t)b * S_ + q0 + rowA + 8) * D_ + h * DK_ + d) = v1;
    }
}

extern "C" void kernel_launch(void* const* d_in, const int* in_sizes, int n_in,
                              void* d_out, int out_size)
{
    const float* query = (const float*)d_in[0];
    const float* key_  = (const float*)d_in[1];
    const float* value = (const float*)d_in[2];
    const int*   mask  = (const int*)d_in[3];
    const float* Wq = (const float*)d_in[4];
    const float* bq = (const float*)d_in[5];
    const float* Wk = (const float*)d_in[6];
    const float* bk = (const float*)d_in[7];
    const float* Wv = (const float*)d_in[8];
    const float* bv = (const float*)d_in[9];
    const float* Wo = (const float*)d_in[10];
    const float* bo = (const float*)d_in[11];
    float* out = (float*)d_out;

    float *gq, *gk, *gv, *gx;
    cudaGetSymbolAddress((void**)&gq, g_q);
    cudaGetSymbolAddress((void**)&gk, g_k);
    cudaGetSymbolAddress((void**)&gv, g_v);
    cudaGetSymbolAddress((void**)&gx, g_x);

    cudaFuncSetAttribute(gemm_mma, cudaFuncAttributeMaxDynamicSharedMemorySize, GK_SMEM);
    cudaFuncSetAttribute(attn_mma, cudaFuncAttributeMaxDynamicSharedMemorySize, ATTN_SMEM_BYTES);

    dim3 gProj(D_ / 128, (B_ * S_) / 128);   // (6, 64)
    gemm_mma<<<gProj, 256, GK_SMEM>>>(query, Wq, bq, gq, 1);
    gemm_mma<<<gProj, 256, GK_SMEM>>>(key_,  Wk, bk, gk, 1);
    gemm_mma<<<gProj, 256, GK_SMEM>>>(value, Wv, bv, gv, 1);

    dim3 gAttn(S_ / 128, H_, B_);            // (16, 12, 4)
    attn_mma<<<gAttn, 256, ATTN_SMEM_BYTES>>>(gq, gk, gv, mask, gx);

    gemm_mma<<<gProj, 256, GK_SMEM>>>(gx, Wo, bo, out, 0);
}

// round 9
// speedup vs baseline: 3.6064x; 1.0419x over previous
#include <cuda_runtime.h>
#include <cstdint>

#define B_  4
#define S_  2048
#define D_  768
#define H_  12
#define DK_ 64

__device__ __forceinline__ uint32_t smem_u32(const void* p) {
    uint32_t a; asm("{ .reg .u64 t; cvta.to.shared.u64 t, %1; cvt.u32.u64 %0, t; }" : "=r"(a) : "l"(p));
    return a;
}
__device__ __forceinline__ void cp_async16(uint32_t dst, const void* src) {
    asm volatile("cp.async.cg.shared.global [%0], [%1], 16;" :: "r"(dst), "l"(src) : "memory");
}
#define CP_COMMIT() asm volatile("cp.async.commit_group;" ::: "memory")
#define CP_WAIT(n)  asm volatile("cp.async.wait_group %0;" :: "n"(n) : "memory")

// m16n8k8 tf32 mma
__device__ __forceinline__ void mma_tf32(float* c, const uint32_t* a, uint32_t b0, uint32_t b1) {
    asm volatile(
        "mma.sync.aligned.m16n8k8.row.col.f32.tf32.tf32.f32 "
        "{%0,%1,%2,%3}, {%4,%5,%6,%7}, {%8,%9}, {%0,%1,%2,%3};"
        : "+f"(c[0]), "+f"(c[1]), "+f"(c[2]), "+f"(c[3])
        : "r"(a[0]), "r"(a[1]), "r"(a[2]), "r"(a[3]), "r"(b0), "r"(b1));
}
// 3xTF32 split
__device__ __forceinline__ void split_tf32(float x, uint32_t& hi, uint32_t& lo) {
    uint32_t xb = __float_as_uint(x);
    hi = xb & 0xFFFFE000u;
    lo = __float_as_uint(x - __uint_as_float(hi));
}

// Scratch
__device__ float g_q[(size_t)B_ * H_ * S_ * DK_];
__device__ float g_k[(size_t)B_ * H_ * S_ * DK_];
__device__ float g_v[(size_t)B_ * H_ * S_ * DK_];
__device__ float g_x[(size_t)B_ * S_ * D_];

// ---------------------------------------------------------------------------
// mma.sync 3xTF32 GEMM body (same math as R7/R8 — passed at rel_err 2.5e-5)
// ---------------------------------------------------------------------------
#define GK_PITCH 36
#define GK_MATF  (128 * GK_PITCH)
#define GK_MATB  (GK_MATF * 4)
#define GK_STAGEF (2 * GK_MATF)
#define GK_STAGEB (2 * GK_MATB)
#define GK_SMEM  (2 * GK_STAGEB)

__device__ __forceinline__ void gemm_body(
    const float* __restrict__ X, const float* __restrict__ W,
    const float* __restrict__ bias, float* __restrict__ out, int scatter)
{
    extern __shared__ float smf[];
    const uint32_t sbase = smem_u32(smf);
    const int tid = threadIdx.x;
    const int lane = tid & 31;
    const int wid = tid >> 5;
    const int wm = (wid & 3) * 32;
    const int wn = (wid >> 2) * 64;
    const int m0 = blockIdx.y * 128;
    const int n0 = blockIdx.x * 128;
    const int g = lane >> 2, t = lane & 3;

    float c[2][8][4];
    #pragma unroll
    for (int mi = 0; mi < 2; mi++)
        #pragma unroll
        for (int nj = 0; nj < 8; nj++)
            #pragma unroll
            for (int q = 0; q < 4; q++) c[mi][nj][q] = 0.0f;

    auto issue = [&](int ch) {
        const int k0 = ch * 32;
        const uint32_t dstA = sbase + (ch & 1) * GK_STAGEB;
        const uint32_t dstB = dstA + GK_MATB;
        #pragma unroll
        for (int i = 0; i < 4; i++) {
            int idx = tid + 256 * i;
            int r = idx >> 3, c4 = idx & 7;
            cp_async16(dstA + r * (GK_PITCH * 4) + c4 * 16,
                       X + (size_t)(m0 + r) * D_ + k0 + c4 * 4);
            cp_async16(dstB + r * (GK_PITCH * 4) + c4 * 16,
                       W + (size_t)(n0 + r) * D_ + k0 + c4 * 4);
        }
        CP_COMMIT();
    };

    issue(0);
    for (int ch = 0; ch < 24; ch++) {
        if (ch + 1 < 24) { issue(ch + 1); CP_WAIT(1); }
        else             { CP_WAIT(0); }
        __syncthreads();

        const float* sA = smf + (ch & 1) * GK_STAGEF;
        const float* sB = sA + GK_MATF;

        #pragma unroll
        for (int k8 = 0; k8 < 4; k8++) {
            const int kb = k8 * 8;
            uint32_t ah[2][4], al[2][4];
            #pragma unroll
            for (int mi = 0; mi < 2; mi++) {
                const int r0 = wm + mi * 16 + g;
                split_tf32(sA[(r0    ) * GK_PITCH + kb + t    ], ah[mi][0], al[mi][0]);
                split_tf32(sA[(r0 + 8) * GK_PITCH + kb + t    ], ah[mi][1], al[mi][1]);
                split_tf32(sA[(r0    ) * GK_PITCH + kb + t + 4], ah[mi][2], al[mi][2]);
                split_tf32(sA[(r0 + 8) * GK_PITCH + kb + t + 4], ah[mi][3], al[mi][3]);
            }
            #pragma unroll
            for (int nj = 0; nj < 8; nj++) {
                const int cn = wn + nj * 8 + g;
                uint32_t bh0, bl0, bh1, bl1;
                split_tf32(sB[cn * GK_PITCH + kb + t    ], bh0, bl0);
                split_tf32(sB[cn * GK_PITCH + kb + t + 4], bh1, bl1);
                mma_tf32(c[0][nj], ah[0], bh0, bh1);
                mma_tf32(c[0][nj], ah[0], bl0, bl1);
                mma_tf32(c[0][nj], al[0], bh0, bh1);
                mma_tf32(c[1][nj], ah[1], bh0, bh1);
                mma_tf32(c[1][nj], ah[1], bl0, bl1);
                mma_tf32(c[1][nj], al[1], bh0, bh1);
            }
        }
        __syncthreads();
    }

    #pragma unroll
    for (int nj = 0; nj < 8; nj++) {
        const int n = n0 + wn + nj * 8 + 2 * t;
        const float2 bb = *(const float2*)(bias + n);
        #pragma unroll
        for (int mi = 0; mi < 2; mi++) {
            #pragma unroll
            for (int half = 0; half < 2; half++) {
                const int m = m0 + wm + mi * 16 + g + 8 * half;
                float2 v;
                v.x = c[mi][nj][2 * half + 0] + bb.x;
                v.y = c[mi][nj][2 * half + 1] + bb.y;
                if (scatter) {
                    const int h = n >> 6, dk = n & 63;
                    const int bi = m >> 11, s = m & 2047;
                    *(float2*)(out + ((((size_t)bi * H_ + h) * S_) + s) * DK_ + dk) = v;
                } else {
                    *(float2*)(out + (size_t)m * D_ + n) = v;
                }
            }
        }
    }
}

// QKV batched projection: blockIdx.z selects (input, weight, bias, output)
__global__ __launch_bounds__(256, 2) void gemm_qkv(
    const float* __restrict__ q, const float* __restrict__ k, const float* __restrict__ v,
    const float* __restrict__ Wq, const float* __restrict__ bq,
    const float* __restrict__ Wk, const float* __restrict__ bk,
    const float* __restrict__ Wv, const float* __restrict__ bv,
    float* __restrict__ gq, float* __restrict__ gk, float* __restrict__ gv)
{
    const int z = blockIdx.z;
    const float* X  = (z == 0) ? q  : (z == 1) ? k  : v;
    const float* W  = (z == 0) ? Wq : (z == 1) ? Wk : Wv;
    const float* bb = (z == 0) ? bq : (z == 1) ? bk : bv;
    float* out      = (z == 0) ? gq : (z == 1) ? gk : gv;
    gemm_body(X, W, bb, out, 1);
}

__global__ __launch_bounds__(256, 2) void gemm_out(
    const float* __restrict__ X, const float* __restrict__ W,
    const float* __restrict__ bias, float* __restrict__ out)
{
    gemm_body(X, W, bias, out, 0);
}

// ---------------------------------------------------------------------------
// Tensor-core flash attention v2: P stays in registers (quad shuffles),
// cp.async double-buffered K/V/mask, ONE barrier per tile.
// ---------------------------------------------------------------------------
#define AQ_OFF  0                          // 128*68 = 8704 floats
#define AK_OFF  8704                       // 2 x 64*68 = 4352 each
#define AV_OFF  (AK_OFF + 2 * 4352)        // 17408; 2 x 64*72 = 4608 each
#define AM_OFF  (AV_OFF + 2 * 4608)        // 26624; 2 x 64 ints
#define ATTN_SMEM_BYTES ((AM_OFF + 128) * 4)   // 107008

__global__ __launch_bounds__(256, 2) void attn_mma(
    const float* __restrict__ gq, const float* __restrict__ gk,
    const float* __restrict__ gv, const int* __restrict__ mask,
    float* __restrict__ gx)
{
    extern __shared__ float sm[];
    const uint32_t sbase = smem_u32(sm);
    float* sQ = sm + AQ_OFF;

    const int tid = threadIdx.x;
    const int wid = tid >> 5;
    const int lane = tid & 31;
    const int g = lane >> 2, t = lane & 3;
    const int q0 = blockIdx.x * 128;
    const int h  = blockIdx.y;
    const int b  = blockIdx.z;
    const int rowA = 16 * wid + g;

    const size_t hb = (((size_t)b * H_ + h) * S_) * DK_;
    const float* Qh = gq + hb;
    const float* Kh = gk + hb;
    const float* Vh = gv + hb;
    const int* mrow = mask + (size_t)b * S_;

    auto issue_kv = [&](int kt, int buf) {
        const uint32_t dK = sbase + (AK_OFF + buf * 4352) * 4;
        const uint32_t dV = sbase + (AV_OFF + buf * 4608) * 4;
        #pragma unroll
        for (int i = 0; i < 4; i++) {
            int idx = tid + 256 * i, r = idx >> 4, c4 = idx & 15;
            cp_async16(dK + r * (68 * 4) + c4 * 16,
                       Kh + (size_t)(kt * 64 + r) * DK_ + c4 * 4);
            cp_async16(dV + r * (72 * 4) + c4 * 16,
                       Vh + (size_t)(kt * 64 + r) * DK_ + c4 * 4);
        }
        if (tid < 16)
            cp_async16(sbase + (AM_OFF + buf * 64) * 4 + tid * 16, mrow + kt * 64 + tid * 4);
        CP_COMMIT();
    };

    // Q tile + first K/V/mask
    issue_kv(0, 0);
    #pragma unroll
    for (int i = 0; i < 8; i++) {
        int idx = tid + 256 * i, r = idx >> 4, c4 = idx & 15;
        *(float4*)(sQ + r * 68 + c4 * 4) = *(const float4*)(Qh + (size_t)(q0 + r) * DK_ + c4 * 4);
    }
    CP_WAIT(0);
    __syncthreads();

    float m0r = -1e30f, m1r = -1e30f, l0 = 0.0f, l1 = 0.0f;
    float co[8][4];
    #pragma unroll
    for (int nj = 0; nj < 8; nj++)
        #pragma unroll
        for (int q = 0; q < 4; q++) co[nj][q] = 0.0f;

    const unsigned FULL = 0xffffffffu;
    const int s0l = 4 * g + (t >> 1);
    const int s1l = s0l + 2;
    const int todd = t & 1;

    for (int kt = 0; kt < S_ / 64; kt++) {
        const int cur = kt & 1;
        const float* sK = sm + AK_OFF + cur * 4352;
        const float* sV = sm + AV_OFF + cur * 4608;
        const int*  sMk = (const int*)(sm + AM_OFF + cur * 64);

        if (kt + 1 < S_ / 64) issue_kv(kt + 1, cur ^ 1);

        // ---- QK^T (3xTF32) ----
        float cs[8][4];
        #pragma unroll
        for (int nj = 0; nj < 8; nj++)
            #pragma unroll
            for (int q = 0; q < 4; q++) cs[nj][q] = 0.0f;

        #pragma unroll
        for (int ks = 0; ks < 8; ks++) {
            const int kb = ks * 8;
            uint32_t ah[4], al[4];
            split_tf32(sQ[(rowA    ) * 68 + kb + t    ], ah[0], al[0]);
            split_tf32(sQ[(rowA + 8) * 68 + kb + t    ], ah[1], al[1]);
            split_tf32(sQ[(rowA    ) * 68 + kb + t + 4], ah[2], al[2]);
            split_tf32(sQ[(rowA + 8) * 68 + kb + t + 4], ah[3], al[3]);
            #pragma unroll
            for (int nj = 0; nj < 8; nj++) {
                uint32_t bh0, bl0, bh1, bl1;
                split_tf32(sK[(g + 8 * nj) * 68 + kb + t    ], bh0, bl0);
                split_tf32(sK[(g + 8 * nj) * 68 + kb + t + 4], bh1, bl1);
                mma_tf32(cs[nj], ah, bh0, bh1);
                mma_tf32(cs[nj], ah, bl0, bl1);
                mma_tf32(cs[nj], al, bh0, bh1);
            }
        }

        // ---- mask + scale + online softmax (row stats in 4-lane quads) ----
        float mx0 = -1e30f, mx1 = -1e30f;
        #pragma unroll
        for (int nj = 0; nj < 8; nj++) {
            const int c0m = sMk[8 * nj + 2 * t];
            const int c1m = sMk[8 * nj + 2 * t + 1];
            cs[nj][0] = c0m ? cs[nj][0] * 0.125f : -1e9f;
            cs[nj][1] = c1m ? cs[nj][1] * 0.125f : -1e9f;
            cs[nj][2] = c0m ? cs[nj][2] * 0.125f : -1e9f;
            cs[nj][3] = c1m ? cs[nj][3] * 0.125f : -1e9f;
            mx0 = fmaxf(mx0, fmaxf(cs[nj][0], cs[nj][1]));
            mx1 = fmaxf(mx1, fmaxf(cs[nj][2], cs[nj][3]));
        }
        #pragma unroll
        for (int d = 1; d < 4; d <<= 1) {
            mx0 = fmaxf(mx0, __shfl_xor_sync(FULL, mx0, d));
            mx1 = fmaxf(mx1, __shfl_xor_sync(FULL, mx1, d));
        }
        const float mn0 = fmaxf(m0r, mx0);
        const float mn1 = fmaxf(m1r, mx1);
        const float cr0 = __expf(m0r - mn0);
        const float cr1 = __expf(m1r - mn1);
        #pragma unroll
        for (int nj = 0; nj < 8; nj++) {
            co[nj][0] *= cr0; co[nj][1] *= cr0;
            co[nj][2] *= cr1; co[nj][3] *= cr1;
        }
        float ps0 = 0.0f, ps1 = 0.0f;
        #pragma unroll
        for (int nj = 0; nj < 8; nj++) {
            cs[nj][0] = __expf(cs[nj][0] - mn0);
            cs[nj][1] = __expf(cs[nj][1] - mn0);
            cs[nj][2] = __expf(cs[nj][2] - mn1);
            cs[nj][3] = __expf(cs[nj][3] - mn1);
            ps0 += cs[nj][0] + cs[nj][1];
            ps1 += cs[nj][2] + cs[nj][3];
        }
        #pragma unroll
        for (int d = 1; d < 4; d <<= 1) {
            ps0 += __shfl_xor_sync(FULL, ps0, d);
            ps1 += __shfl_xor_sync(FULL, ps1, d);
        }
        l0 = l0 * cr0 + ps0;
        l1 = l1 * cr1 + ps1;
        m0r = mn0; m1r = mn1;

        // ---- PV (3xTF32): P A-fragments built by quad shuffles from cs ----
        #pragma unroll
        for (int ks = 0; ks < 8; ks++) {
            // A-frag cols {t, t+4} of key-block ks from C-layout cols {2t,2t+1}
            float x0 = __shfl_sync(FULL, cs[ks][0], s0l, 4 * 8); // width 32 default
            float x1 = __shfl_sync(FULL, cs[ks][1], s0l);
            float x2 = __shfl_sync(FULL, cs[ks][2], s0l);
            float x3 = __shfl_sync(FULL, cs[ks][3], s0l);
            float y0 = __shfl_sync(FULL, cs[ks][0], s1l);
            float y1 = __shfl_sync(FULL, cs[ks][1], s1l);
            float y2 = __shfl_sync(FULL, cs[ks][2], s1l);
            float y3 = __shfl_sync(FULL, cs[ks][3], s1l);
            float a0 = todd ? x1 : x0;   // P[rowA][8ks+t]
            float a1 = todd ? x3 : x2;   // P[rowA+8][8ks+t]
            float a2 = todd ? y1 : y0;   // P[rowA][8ks+t+4]
            float a3 = todd ? y3 : y2;   // P[rowA+8][8ks+t+4]
            uint32_t ah[4], al[4];
            split_tf32(a0, ah[0], al[0]);
            split_tf32(a1, ah[1], al[1]);
            split_tf32(a2, ah[2], al[2]);
            split_tf32(a3, ah[3], al[3]);
            const int kb = ks * 8;
            #pragma unroll
            for (int nj = 0; nj < 8; nj++) {
                uint32_t bh0, bl0, bh1, bl1;
                split_tf32(sV[(kb + t    ) * 72 + 8 * nj + g], bh0, bl0);
                split_tf32(sV[(kb + t + 4) * 72 + 8 * nj + g], bh1, bl1);
                mma_tf32(co[nj], ah, bh0, bh1);
                mma_tf32(co[nj], ah, bl0, bl1);
                mma_tf32(co[nj], al, bh0, bh1);
            }
        }

        if (kt + 1 < S_ / 64) CP_WAIT(0);
        __syncthreads();   // all warps done with cur buffers; next buffers landed
    }

    // ---- finalize ----
    const float inv0 = 1.0f / l0;
    const float inv1 = 1.0f / l1;
    #pragma unroll
    for (int nj = 0; nj < 8; nj++) {
        const int d = 8 * nj + 2 * t;
        float2 v0 = make_float2(co[nj][0] * inv0, co[nj][1] * inv0);
        float2 v1 = make_float2(co[nj][2] * inv1, co[nj][3] * inv1);
        *(float2*)(gx + ((size_t)b * S_ + q0 + rowA    ) * D_ + h * DK_ + d) = v0;
        *(float2*)(gx + ((size_t)b * S_ + q0 + rowA + 8) * D_ + h * DK_ + d) = v1;
    }
}

extern "C" void kernel_launch(void* const* d_in, const int* in_sizes, int n_in,
                              void* d_out, int out_size)
{
    const float* query = (const float*)d_in[0];
    const float* key_  = (const float*)d_in[1];
    const float* value = (const float*)d_in[2];
    const int*   mask  = (const int*)d_in[3];
    const float* Wq = (const float*)d_in[4];
    const float* bq = (const float*)d_in[5];
    const float* Wk = (const float*)d_in[6];
    const float* bk = (const float*)d_in[7];
    const float* Wv = (const float*)d_in[8];
    const float* bv = (const float*)d_in[9];
    const float* Wo = (const float*)d_in[10];
    const float* bo = (const float*)d_in[11];
    float* out = (float*)d_out;

    float *gq, *gk, *gv, *gx;
    cudaGetSymbolAddress((void**)&gq, g_q);
    cudaGetSymbolAddress((void**)&gk, g_k);
    cudaGetSymbolAddress((void**)&gv, g_v);
    cudaGetSymbolAddress((void**)&gx, g_x);

    cudaFuncSetAttribute(gemm_qkv, cudaFuncAttributeMaxDynamicSharedMemorySize, GK_SMEM);
    cudaFuncSetAttribute(gemm_out, cudaFuncAttributeMaxDynamicSharedMemorySize, GK_SMEM);
    cudaFuncSetAttribute(attn_mma, cudaFuncAttributeMaxDynamicSharedMemorySize, ATTN_SMEM_BYTES);

    dim3 gProj(D_ / 128, (B_ * S_) / 128, 3);   // (6, 64, 3)
    gemm_qkv<<<gProj, 256, GK_SMEM>>>(query, key_, value, Wq, bq, Wk, bk, Wv, bv, gq, gk, gv);

    dim3 gAttn(S_ / 128, H_, B_);               // (16, 12, 4)
    attn_mma<<<gAttn, 256, ATTN_SMEM_BYTES>>>(gq, gk, gv, mask, gx);

    dim3 gOut(D_ / 128, (B_ * S_) / 128);       // (6, 64)
    gemm_out<<<gOut, 256, GK_SMEM>>>(gx, Wo, bo, out);
}

// round 10
// speedup vs baseline: 4.9229x; 1.3651x over previous
#include <cuda_runtime.h>
#include <cstdint>

#define B_  4
#define S_  2048
#define D_  768
#define H_  12
#define DK_ 64

__device__ __forceinline__ uint32_t smem_u32(const void* p) {
    uint32_t a; asm("{ .reg .u64 t; cvta.to.shared.u64 t, %1; cvt.u32.u64 %0, t; }" : "=r"(a) : "l"(p));
    return a;
}
__device__ __forceinline__ void cp_async16(uint32_t dst, const void* src) {
    asm volatile("cp.async.cg.shared.global [%0], [%1], 16;" :: "r"(dst), "l"(src) : "memory");
}
#define CP_COMMIT() asm volatile("cp.async.commit_group;" ::: "memory")
#define CP_WAIT(n)  asm volatile("cp.async.wait_group %0;" :: "n"(n) : "memory")

// m16n8k8 tf32 mma
__device__ __forceinline__ void mma_tf32(float* c, const uint32_t* a, uint32_t b0, uint32_t b1) {
    asm volatile(
        "mma.sync.aligned.m16n8k8.row.col.f32.tf32.tf32.f32 "
        "{%0,%1,%2,%3}, {%4,%5,%6,%7}, {%8,%9}, {%0,%1,%2,%3};"
        : "+f"(c[0]), "+f"(c[1]), "+f"(c[2]), "+f"(c[3])
        : "r"(a[0]), "r"(a[1]), "r"(a[2]), "r"(a[3]), "r"(b0), "r"(b1));
}
// 3xTF32 split (projections)
__device__ __forceinline__ void split_tf32(float x, uint32_t& hi, uint32_t& lo) {
    uint32_t xb = __float_as_uint(x);
    hi = xb & 0xFFFFE000u;
    lo = __float_as_uint(x - __uint_as_float(hi));
}
// round-to-nearest tf32 (attention)
__device__ __forceinline__ uint32_t to_tf32(float x) {
    uint32_t r; asm("cvt.rna.tf32.f32 %0,%1;" : "=r"(r) : "f"(x)); return r;
}

// Scratch
__device__ float g_q[(size_t)B_ * H_ * S_ * DK_];
__device__ float g_k[(size_t)B_ * H_ * S_ * DK_];
__device__ float g_v[(size_t)B_ * H_ * S_ * DK_];
__device__ float g_x[(size_t)B_ * S_ * D_];

// ---------------------------------------------------------------------------
// mma.sync 3xTF32 GEMM body (unchanged — rel_err 2.5e-5 contribution)
// ---------------------------------------------------------------------------
#define GK_PITCH 36
#define GK_MATF  (128 * GK_PITCH)
#define GK_MATB  (GK_MATF * 4)
#define GK_STAGEF (2 * GK_MATF)
#define GK_STAGEB (2 * GK_MATB)
#define GK_SMEM  (2 * GK_STAGEB)

__device__ __forceinline__ void gemm_body(
    const float* __restrict__ X, const float* __restrict__ W,
    const float* __restrict__ bias, float* __restrict__ out, int scatter)
{
    extern __shared__ float smf[];
    const uint32_t sbase = smem_u32(smf);
    const int tid = threadIdx.x;
    const int lane = tid & 31;
    const int wid = tid >> 5;
    const int wm = (wid & 3) * 32;
    const int wn = (wid >> 2) * 64;
    const int m0 = blockIdx.y * 128;
    const int n0 = blockIdx.x * 128;
    const int g = lane >> 2, t = lane & 3;

    float c[2][8][4];
    #pragma unroll
    for (int mi = 0; mi < 2; mi++)
        #pragma unroll
        for (int nj = 0; nj < 8; nj++)
            #pragma unroll
            for (int q = 0; q < 4; q++) c[mi][nj][q] = 0.0f;

    auto issue = [&](int ch) {
        const int k0 = ch * 32;
        const uint32_t dstA = sbase + (ch & 1) * GK_STAGEB;
        const uint32_t dstB = dstA + GK_MATB;
        #pragma unroll
        for (int i = 0; i < 4; i++) {
            int idx = tid + 256 * i;
            int r = idx >> 3, c4 = idx & 7;
            cp_async16(dstA + r * (GK_PITCH * 4) + c4 * 16,
                       X + (size_t)(m0 + r) * D_ + k0 + c4 * 4);
            cp_async16(dstB + r * (GK_PITCH * 4) + c4 * 16,
                       W + (size_t)(n0 + r) * D_ + k0 + c4 * 4);
        }
        CP_COMMIT();
    };

    issue(0);
    for (int ch = 0; ch < 24; ch++) {
        if (ch + 1 < 24) { issue(ch + 1); CP_WAIT(1); }
        else             { CP_WAIT(0); }
        __syncthreads();

        const float* sA = smf + (ch & 1) * GK_STAGEF;
        const float* sB = sA + GK_MATF;

        #pragma unroll
        for (int k8 = 0; k8 < 4; k8++) {
            const int kb = k8 * 8;
            uint32_t ah[2][4], al[2][4];
            #pragma unroll
            for (int mi = 0; mi < 2; mi++) {
                const int r0 = wm + mi * 16 + g;
                split_tf32(sA[(r0    ) * GK_PITCH + kb + t    ], ah[mi][0], al[mi][0]);
                split_tf32(sA[(r0 + 8) * GK_PITCH + kb + t    ], ah[mi][1], al[mi][1]);
                split_tf32(sA[(r0    ) * GK_PITCH + kb + t + 4], ah[mi][2], al[mi][2]);
                split_tf32(sA[(r0 + 8) * GK_PITCH + kb + t + 4], ah[mi][3], al[mi][3]);
            }
            #pragma unroll
            for (int nj = 0; nj < 8; nj++) {
                const int cn = wn + nj * 8 + g;
                uint32_t bh0, bl0, bh1, bl1;
                split_tf32(sB[cn * GK_PITCH + kb + t    ], bh0, bl0);
                split_tf32(sB[cn * GK_PITCH + kb + t + 4], bh1, bl1);
                mma_tf32(c[0][nj], ah[0], bh0, bh1);
                mma_tf32(c[0][nj], ah[0], bl0, bl1);
                mma_tf32(c[0][nj], al[0], bh0, bh1);
                mma_tf32(c[1][nj], ah[1], bh0, bh1);
                mma_tf32(c[1][nj], ah[1], bl0, bl1);
                mma_tf32(c[1][nj], al[1], bh0, bh1);
            }
        }
        __syncthreads();
    }

    #pragma unroll
    for (int nj = 0; nj < 8; nj++) {
        const int n = n0 + wn + nj * 8 + 2 * t;
        const float2 bb = *(const float2*)(bias + n);
        #pragma unroll
        for (int mi = 0; mi < 2; mi++) {
            #pragma unroll
            for (int half = 0; half < 2; half++) {
                const int m = m0 + wm + mi * 16 + g + 8 * half;
                float2 v;
                v.x = c[mi][nj][2 * half + 0] + bb.x;
                v.y = c[mi][nj][2 * half + 1] + bb.y;
                if (scatter) {
                    const int h = n >> 6, dk = n & 63;
                    const int bi = m >> 11, s = m & 2047;
                    *(float2*)(out + ((((size_t)bi * H_ + h) * S_) + s) * DK_ + dk) = v;
                } else {
                    *(float2*)(out + (size_t)m * D_ + n) = v;
                }
            }
        }
    }
}

__global__ __launch_bounds__(256, 2) void gemm_qkv(
    const float* __restrict__ q, const float* __restrict__ k, const float* __restrict__ v,
    const float* __restrict__ Wq, const float* __restrict__ bq,
    const float* __restrict__ Wk, const float* __restrict__ bk,
    const float* __restrict__ Wv, const float* __restrict__ bv,
    float* __restrict__ gq, float* __restrict__ gk, float* __restrict__ gv)
{
    const int z = blockIdx.z;
    const float* X  = (z == 0) ? q  : (z == 1) ? k  : v;
    const float* W  = (z == 0) ? Wq : (z == 1) ? Wk : Wv;
    const float* bb = (z == 0) ? bq : (z == 1) ? bk : bv;
    float* out      = (z == 0) ? gq : (z == 1) ? gk : gv;
    gemm_body(X, W, bb, out, 1);
}

__global__ __launch_bounds__(256, 2) void gemm_out(
    const float* __restrict__ X, const float* __restrict__ W,
    const float* __restrict__ bias, float* __restrict__ out)
{
    gemm_body(X, W, bias, out, 0);
}

// ---------------------------------------------------------------------------
// Tensor-core flash attention v3: 1xTF32 (RN) for QK^T and PV,
// P in registers via quad shuffles, cp.async double-buffered K/V/mask.
// ---------------------------------------------------------------------------
#define AQ_OFF  0                          // 128*68 = 8704 floats
#define AK_OFF  8704                       // 2 x 64*68 = 4352 each
#define AV_OFF  (AK_OFF + 2 * 4352)        // 17408; 2 x 64*72 = 4608 each
#define AM_OFF  (AV_OFF + 2 * 4608)        // 26624; 2 x 64 ints
#define ATTN_SMEM_BYTES ((AM_OFF + 128) * 4)   // 107008

__global__ __launch_bounds__(256, 2) void attn_mma(
    const float* __restrict__ gq, const float* __restrict__ gk,
    const float* __restrict__ gv, const int* __restrict__ mask,
    float* __restrict__ gx)
{
    extern __shared__ float sm[];
    const uint32_t sbase = smem_u32(sm);
    float* sQ = sm + AQ_OFF;

    const int tid = threadIdx.x;
    const int wid = tid >> 5;
    const int lane = tid & 31;
    const int g = lane >> 2, t = lane & 3;
    const int q0 = blockIdx.x * 128;
    const int h  = blockIdx.y;
    const int b  = blockIdx.z;
    const int rowA = 16 * wid + g;

    const size_t hb = (((size_t)b * H_ + h) * S_) * DK_;
    const float* Qh = gq + hb;
    const float* Kh = gk + hb;
    const float* Vh = gv + hb;
    const int* mrow = mask + (size_t)b * S_;

    auto issue_kv = [&](int kt, int buf) {
        const uint32_t dK = sbase + (AK_OFF + buf * 4352) * 4;
        const uint32_t dV = sbase + (AV_OFF + buf * 4608) * 4;
        #pragma unroll
        for (int i = 0; i < 4; i++) {
            int idx = tid + 256 * i, r = idx >> 4, c4 = idx & 15;
            cp_async16(dK + r * (68 * 4) + c4 * 16,
                       Kh + (size_t)(kt * 64 + r) * DK_ + c4 * 4);
            cp_async16(dV + r * (72 * 4) + c4 * 16,
                       Vh + (size_t)(kt * 64 + r) * DK_ + c4 * 4);
        }
        if (tid < 16)
            cp_async16(sbase + (AM_OFF + buf * 64) * 4 + tid * 16, mrow + kt * 64 + tid * 4);
        CP_COMMIT();
    };

    issue_kv(0, 0);
    #pragma unroll
    for (int i = 0; i < 8; i++) {
        int idx = tid + 256 * i, r = idx >> 4, c4 = idx & 15;
        *(float4*)(sQ + r * 68 + c4 * 4) = *(const float4*)(Qh + (size_t)(q0 + r) * DK_ + c4 * 4);
    }
    CP_WAIT(0);
    __syncthreads();

    float m0r = -1e30f, m1r = -1e30f, l0 = 0.0f, l1 = 0.0f;
    float co[8][4];
    #pragma unroll
    for (int nj = 0; nj < 8; nj++)
        #pragma unroll
        for (int q = 0; q < 4; q++) co[nj][q] = 0.0f;

    const unsigned FULL = 0xffffffffu;
    const int s0l = 4 * g + (t >> 1);
    const int s1l = s0l + 2;
    const int todd = t & 1;

    for (int kt = 0; kt < S_ / 64; kt++) {
        const int cur = kt & 1;
        const float* sK = sm + AK_OFF + cur * 4352;
        const float* sV = sm + AV_OFF + cur * 4608;
        const int*  sMk = (const int*)(sm + AM_OFF + cur * 64);

        if (kt + 1 < S_ / 64) issue_kv(kt + 1, cur ^ 1);

        // ---- QK^T (1xTF32, RN) ----
        float cs[8][4];
        #pragma unroll
        for (int nj = 0; nj < 8; nj++)
            #pragma unroll
            for (int q = 0; q < 4; q++) cs[nj][q] = 0.0f;

        #pragma unroll
        for (int ks = 0; ks < 8; ks++) {
            const int kb = ks * 8;
            uint32_t a[4];
            a[0] = to_tf32(sQ[(rowA    ) * 68 + kb + t    ]);
            a[1] = to_tf32(sQ[(rowA + 8) * 68 + kb + t    ]);
            a[2] = to_tf32(sQ[(rowA    ) * 68 + kb + t + 4]);
            a[3] = to_tf32(sQ[(rowA + 8) * 68 + kb + t + 4]);
            #pragma unroll
            for (int nj = 0; nj < 8; nj++) {
                uint32_t b0 = to_tf32(sK[(g + 8 * nj) * 68 + kb + t    ]);
                uint32_t b1 = to_tf32(sK[(g + 8 * nj) * 68 + kb + t + 4]);
                mma_tf32(cs[nj], a, b0, b1);
            }
        }

        // ---- mask + scale + online softmax ----
        float mx0 = -1e30f, mx1 = -1e30f;
        #pragma unroll
        for (int nj = 0; nj < 8; nj++) {
            const int c0m = sMk[8 * nj + 2 * t];
            const int c1m = sMk[8 * nj + 2 * t + 1];
            cs[nj][0] = c0m ? cs[nj][0] * 0.125f : -1e9f;
            cs[nj][1] = c1m ? cs[nj][1] * 0.125f : -1e9f;
            cs[nj][2] = c0m ? cs[nj][2] * 0.125f : -1e9f;
            cs[nj][3] = c1m ? cs[nj][3] * 0.125f : -1e9f;
            mx0 = fmaxf(mx0, fmaxf(cs[nj][0], cs[nj][1]));
            mx1 = fmaxf(mx1, fmaxf(cs[nj][2], cs[nj][3]));
        }
        #pragma unroll
        for (int d = 1; d < 4; d <<= 1) {
            mx0 = fmaxf(mx0, __shfl_xor_sync(FULL, mx0, d));
            mx1 = fmaxf(mx1, __shfl_xor_sync(FULL, mx1, d));
        }
        const float mn0 = fmaxf(m0r, mx0);
        const float mn1 = fmaxf(m1r, mx1);
        const float cr0 = __expf(m0r - mn0);
        const float cr1 = __expf(m1r - mn1);
        #pragma unroll
        for (int nj = 0; nj < 8; nj++) {
            co[nj][0] *= cr0; co[nj][1] *= cr0;
            co[nj][2] *= cr1; co[nj][3] *= cr1;
        }
        float ps0 = 0.0f, ps1 = 0.0f;
        #pragma unroll
        for (int nj = 0; nj < 8; nj++) {
            cs[nj][0] = __expf(cs[nj][0] - mn0);
            cs[nj][1] = __expf(cs[nj][1] - mn0);
            cs[nj][2] = __expf(cs[nj][2] - mn1);
            cs[nj][3] = __expf(cs[nj][3] - mn1);
            ps0 += cs[nj][0] + cs[nj][1];
            ps1 += cs[nj][2] + cs[nj][3];
        }
        #pragma unroll
        for (int d = 1; d < 4; d <<= 1) {
            ps0 += __shfl_xor_sync(FULL, ps0, d);
            ps1 += __shfl_xor_sync(FULL, ps1, d);
        }
        l0 = l0 * cr0 + ps0;
        l1 = l1 * cr1 + ps1;
        m0r = mn0; m1r = mn1;

        // ---- PV (1xTF32, RN): P A-fragments via quad shuffles ----
        #pragma unroll
        for (int ks = 0; ks < 8; ks++) {
            float x0 = __shfl_sync(FULL, cs[ks][0], s0l);
            float x1 = __shfl_sync(FULL, cs[ks][1], s0l);
            float x2 = __shfl_sync(FULL, cs[ks][2], s0l);
            float x3 = __shfl_sync(FULL, cs[ks][3], s0l);
            float y0 = __shfl_sync(FULL, cs[ks][0], s1l);
            float y1 = __shfl_sync(FULL, cs[ks][1], s1l);
            float y2 = __shfl_sync(FULL, cs[ks][2], s1l);
            float y3 = __shfl_sync(FULL, cs[ks][3], s1l);
            uint32_t a[4];
            a[0] = to_tf32(todd ? x1 : x0);   // P[rowA][8ks+t]
            a[1] = to_tf32(todd ? x3 : x2);   // P[rowA+8][8ks+t]
            a[2] = to_tf32(todd ? y1 : y0);   // P[rowA][8ks+t+4]
            a[3] = to_tf32(todd ? y3 : y2);   // P[rowA+8][8ks+t+4]
            const int kb = ks * 8;
            #pragma unroll
            for (int nj = 0; nj < 8; nj++) {
                uint32_t b0 = to_tf32(sV[(kb + t    ) * 72 + 8 * nj + g]);
                uint32_t b1 = to_tf32(sV[(kb + t + 4) * 72 + 8 * nj + g]);
                mma_tf32(co[nj], a, b0, b1);
            }
        }

        if (kt + 1 < S_ / 64) CP_WAIT(0);
        __syncthreads();
    }

    // ---- finalize ----
    const float inv0 = 1.0f / l0;
    const float inv1 = 1.0f / l1;
    #pragma unroll
    for (int nj = 0; nj < 8; nj++) {
        const int d = 8 * nj + 2 * t;
        float2 v0 = make_float2(co[nj][0] * inv0, co[nj][1] * inv0);
        float2 v1 = make_float2(co[nj][2] * inv1, co[nj][3] * inv1);
        *(float2*)(gx + ((size_t)b * S_ + q0 + rowA    ) * D_ + h * DK_ + d) = v0;
        *(float2*)(gx + ((size_t)b * S_ + q0 + rowA + 8) * D_ + h * DK_ + d) = v1;
    }
}

extern "C" void kernel_launch(void* const* d_in, const int* in_sizes, int n_in,
                              void* d_out, int out_size)
{
    const float* query = (const float*)d_in[0];
    const float* key_  = (const float*)d_in[1];
    const float* value = (const float*)d_in[2];
    const int*   mask  = (const int*)d_in[3];
    const float* Wq = (const float*)d_in[4];
    const float* bq = (const float*)d_in[5];
    const float* Wk = (const float*)d_in[6];
    const float* bk = (const float*)d_in[7];
    const float* Wv = (const float*)d_in[8];
    const float* bv = (const float*)d_in[9];
    const float* Wo = (const float*)d_in[10];
    const float* bo = (const float*)d_in[11];
    float* out = (float*)d_out;

    float *gq, *gk, *gv, *gx;
    cudaGetSymbolAddress((void**)&gq, g_q);
    cudaGetSymbolAddress((void**)&gk, g_k);
    cudaGetSymbolAddress((void**)&gv, g_v);
    cudaGetSymbolAddress((void**)&gx, g_x);

    cudaFuncSetAttribute(gemm_qkv, cudaFuncAttributeMaxDynamicSharedMemorySize, GK_SMEM);
    cudaFuncSetAttribute(gemm_out, cudaFuncAttributeMaxDynamicSharedMemorySize, GK_SMEM);
    cudaFuncSetAttribute(attn_mma, cudaFuncAttributeMaxDynamicSharedMemorySize, ATTN_SMEM_BYTES);

    dim3 gProj(D_ / 128, (B_ * S_) / 128, 3);   // (6, 64, 3)
    gemm_qkv<<<gProj, 256, GK_SMEM>>>(query, key_, value, Wq, bq, Wk, bk, Wv, bv, gq, gk, gv);

    dim3 gAttn(S_ / 128, H_, B_);               // (16, 12, 4)
    attn_mma<<<gAttn, 256, ATTN_SMEM_BYTES>>>(gq, gk, gv, mask, gx);

    dim3 gOut(D_ / 128, (B_ * S_) / 128);       // (6, 64)
    gemm_out<<<gOut, 256, GK_SMEM>>>(gx, Wo, bo, out);
}

// round 12
// speedup vs baseline: 5.8281x; 1.1839x over previous
#include <cuda_runtime.h>
#include <cstdint>

#define B_  4
#define S_  2048
#define D_  768
#define H_  12
#define DK_ 64

__device__ __forceinline__ uint32_t smem_u32(const void* p) {
    uint32_t a; asm("{ .reg .u64 t; cvta.to.shared.u64 t, %1; cvt.u32.u64 %0, t; }" : "=r"(a) : "l"(p));
    return a;
}
__device__ __forceinline__ void cp_async16(uint32_t dst, const void* src) {
    asm volatile("cp.async.cg.shared.global [%0], [%1], 16;" :: "r"(dst), "l"(src) : "memory");
}
#define CP_COMMIT() asm volatile("cp.async.commit_group;" ::: "memory")
#define CP_WAIT(n)  asm volatile("cp.async.wait_group %0;" :: "n"(n) : "memory")

// m16n8k8 tf32 mma (attention)
__device__ __forceinline__ void mma_tf32(float* c, const uint32_t* a, uint32_t b0, uint32_t b1) {
    asm volatile(
        "mma.sync.aligned.m16n8k8.row.col.f32.tf32.tf32.f32 "
        "{%0,%1,%2,%3}, {%4,%5,%6,%7}, {%8,%9}, {%0,%1,%2,%3};"
        : "+f"(c[0]), "+f"(c[1]), "+f"(c[2]), "+f"(c[3])
        : "r"(a[0]), "r"(a[1]), "r"(a[2]), "r"(a[3]), "r"(b0), "r"(b1));
}
// m16n8k16 bf16 mma (projections)
__device__ __forceinline__ void mma_bf16(float* c, const uint32_t* a, uint32_t b0, uint32_t b1) {
    asm volatile(
        "mma.sync.aligned.m16n8k16.row.col.f32.bf16.bf16.f32 "
        "{%0,%1,%2,%3}, {%4,%5,%6,%7}, {%8,%9}, {%0,%1,%2,%3};"
        : "+f"(c[0]), "+f"(c[1]), "+f"(c[2]), "+f"(c[3])
        : "r"(a[0]), "r"(a[1]), "r"(a[2]), "r"(a[3]), "r"(b0), "r"(b1));
}
// bf16x3 pack: hi = bf16x2(x0,x1) (low k in low half), lo = bf16x2 of exact residuals
__device__ __forceinline__ void bf16x3_pack(float x0, float x1, uint32_t& hi, uint32_t& lo) {
    asm("cvt.rn.bf16x2.f32 %0, %1, %2;" : "=r"(hi) : "f"(x1), "f"(x0));
    float h0 = __uint_as_float(hi << 16);
    float h1 = __uint_as_float(hi & 0xFFFF0000u);
    float r0 = x0 - h0;
    float r1 = x1 - h1;
    asm("cvt.rn.bf16x2.f32 %0, %1, %2;" : "=r"(lo) : "f"(r1), "f"(r0));
}
// round-to-nearest tf32 (attention)
__device__ __forceinline__ uint32_t to_tf32(float x) {
    uint32_t r; asm("cvt.rna.tf32.f32 %0,%1;" : "=r"(r) : "f"(x)); return r;
}

// Scratch
__device__ float g_q[(size_t)B_ * H_ * S_ * DK_];
__device__ float g_k[(size_t)B_ * H_ * S_ * DK_];
__device__ float g_v[(size_t)B_ * H_ * S_ * DK_];
__device__ float g_x[(size_t)B_ * S_ * D_];

// ---------------------------------------------------------------------------
// bf16x3 GEMM body: Y[m,n] = X[m,:].W[n,:] + bias[n].
// CTA 128x128, 8 warps (4Mx2N), K chunks of 32, cp.async double-buffered.
// A*B = Ah*Bh + Ah*Bl + Al*Bh with bf16 hi/lo (16 mantissa bits captured).
// ---------------------------------------------------------------------------
#define GK_PITCH 36
#define GK_MATF  (128 * GK_PITCH)
#define GK_MATB  (GK_MATF * 4)
#define GK_STAGEF (2 * GK_MATF)
#define GK_STAGEB (2 * GK_MATB)
#define GK_SMEM  (2 * GK_STAGEB)

__device__ __forceinline__ void gemm_body(
    const float* __restrict__ X, const float* __restrict__ W,
    const float* __restrict__ bias, float* __restrict__ out, int scatter)
{
    extern __shared__ float smf[];
    const uint32_t sbase = smem_u32(smf);
    const int tid = threadIdx.x;
    const int lane = tid & 31;
    const int wid = tid >> 5;
    const int wm = (wid & 3) * 32;
    const int wn = (wid >> 2) * 64;
    const int m0 = blockIdx.y * 128;
    const int n0 = blockIdx.x * 128;
    const int g = lane >> 2, t = lane & 3;

    float c[2][8][4];
    #pragma unroll
    for (int mi = 0; mi < 2; mi++)
        #pragma unroll
        for (int nj = 0; nj < 8; nj++)
            #pragma unroll
            for (int q = 0; q < 4; q++) c[mi][nj][q] = 0.0f;

    auto issue = [&](int ch) {
        const int k0 = ch * 32;
        const uint32_t dstA = sbase + (ch & 1) * GK_STAGEB;
        const uint32_t dstB = dstA + GK_MATB;
        #pragma unroll
        for (int i = 0; i < 4; i++) {
            int idx = tid + 256 * i;
            int r = idx >> 3, c4 = idx & 7;
            cp_async16(dstA + r * (GK_PITCH * 4) + c4 * 16,
                       X + (size_t)(m0 + r) * D_ + k0 + c4 * 4);
            cp_async16(dstB + r * (GK_PITCH * 4) + c4 * 16,
                       W + (size_t)(n0 + r) * D_ + k0 + c4 * 4);
        }
        CP_COMMIT();
    };

    issue(0);
    for (int ch = 0; ch < 24; ch++) {
        if (ch + 1 < 24) { issue(ch + 1); CP_WAIT(1); }
        else             { CP_WAIT(0); }
        __syncthreads();

        const float* sA = smf + (ch & 1) * GK_STAGEF;
        const float* sB = sA + GK_MATF;

        #pragma unroll
        for (int k16 = 0; k16 < 2; k16++) {
            const int kb = k16 * 16;
            uint32_t ah[2][4], al[2][4];
            #pragma unroll
            for (int mi = 0; mi < 2; mi++) {
                const int r0 = wm + mi * 16 + g;
                float2 p0 = *(const float2*)(sA + (r0    ) * GK_PITCH + kb + 2 * t);
                float2 p1 = *(const float2*)(sA + (r0 + 8) * GK_PITCH + kb + 2 * t);
                float2 p2 = *(const float2*)(sA + (r0    ) * GK_PITCH + kb + 2 * t + 8);
                float2 p3 = *(const float2*)(sA + (r0 + 8) * GK_PITCH + kb + 2 * t + 8);
                bf16x3_pack(p0.x, p0.y, ah[mi][0], al[mi][0]);
                bf16x3_pack(p1.x, p1.y, ah[mi][1], al[mi][1]);
                bf16x3_pack(p2.x, p2.y, ah[mi][2], al[mi][2]);
                bf16x3_pack(p3.x, p3.y, ah[mi][3], al[mi][3]);
            }
            #pragma unroll
            for (int nj = 0; nj < 8; nj++) {
                const int cn = wn + nj * 8 + g;
                float2 q0 = *(const float2*)(sB + cn * GK_PITCH + kb + 2 * t);
                float2 q1 = *(const float2*)(sB + cn * GK_PITCH + kb + 2 * t + 8);
                uint32_t bh0, bl0, bh1, bl1;
                bf16x3_pack(q0.x, q0.y, bh0, bl0);
                bf16x3_pack(q1.x, q1.y, bh1, bl1);
                mma_bf16(c[0][nj], ah[0], bh0, bh1);
                mma_bf16(c[0][nj], ah[0], bl0, bl1);
                mma_bf16(c[0][nj], al[0], bh0, bh1);
                mma_bf16(c[1][nj], ah[1], bh0, bh1);
                mma_bf16(c[1][nj], ah[1], bl0, bl1);
                mma_bf16(c[1][nj], al[1], bh0, bh1);
            }
        }
        __syncthreads();
    }

    #pragma unroll
    for (int nj = 0; nj < 8; nj++) {
        const int n = n0 + wn + nj * 8 + 2 * t;
        const float2 bb = *(const float2*)(bias + n);
        #pragma unroll
        for (int mi = 0; mi < 2; mi++) {
            #pragma unroll
            for (int half = 0; half < 2; half++) {
                const int m = m0 + wm + mi * 16 + g + 8 * half;
                float2 v;
                v.x = c[mi][nj][2 * half + 0] + bb.x;
                v.y = c[mi][nj][2 * half + 1] + bb.y;
                if (scatter) {
                    const int h = n >> 6, dk = n & 63;
                    const int bi = m >> 11, s = m & 2047;
                    *(float2*)(out + ((((size_t)bi * H_ + h) * S_) + s) * DK_ + dk) = v;
                } else {
                    *(float2*)(out + (size_t)m * D_ + n) = v;
                }
            }
        }
    }
}

__global__ __launch_bounds__(256, 2) void gemm_qkv(
    const float* __restrict__ q, const float* __restrict__ k, const float* __restrict__ v,
    const float* __restrict__ Wq, const float* __restrict__ bq,
    const float* __restrict__ Wk, const float* __restrict__ bk,
    const float* __restrict__ Wv, const float* __restrict__ bv,
    float* __restrict__ gq, float* __restrict__ gk, float* __restrict__ gv)
{
    const int z = blockIdx.z;
    const float* X  = (z == 0) ? q  : (z == 1) ? k  : v;
    const float* W  = (z == 0) ? Wq : (z == 1) ? Wk : Wv;
    const float* bb = (z == 0) ? bq : (z == 1) ? bk : bv;
    float* out      = (z == 0) ? gq : (z == 1) ? gk : gv;
    gemm_body(X, W, bb, out, 1);
}

__global__ __launch_bounds__(256, 2) void gemm_out(
    const float* __restrict__ X, const float* __restrict__ W,
    const float* __restrict__ bias, float* __restrict__ out)
{
    gemm_body(X, W, bias, out, 0);
}

// ---------------------------------------------------------------------------
// Tensor-core flash attention v3 (unchanged — 1xTF32 RN, P in registers,
// cp.async double-buffered K/V/mask).
// ---------------------------------------------------------------------------
#define AQ_OFF  0
#define AK_OFF  8704
#define AV_OFF  (AK_OFF + 2 * 4352)
#define AM_OFF  (AV_OFF + 2 * 4608)
#define ATTN_SMEM_BYTES ((AM_OFF + 128) * 4)

__global__ __launch_bounds__(256, 2) void attn_mma(
    const float* __restrict__ gq, const float* __restrict__ gk,
    const float* __restrict__ gv, const int* __restrict__ mask,
    float* __restrict__ gx)
{
    extern __shared__ float sm[];
    const uint32_t sbase = smem_u32(sm);
    float* sQ = sm + AQ_OFF;

    const int tid = threadIdx.x;
    const int wid = tid >> 5;
    const int lane = tid & 31;
    const int g = lane >> 2, t = lane & 3;
    const int q0 = blockIdx.x * 128;
    const int h  = blockIdx.y;
    const int b  = blockIdx.z;
    const int rowA = 16 * wid + g;

    const size_t hb = (((size_t)b * H_ + h) * S_) * DK_;
    const float* Qh = gq + hb;
    const float* Kh = gk + hb;
    const float* Vh = gv + hb;
    const int* mrow = mask + (size_t)b * S_;

    auto issue_kv = [&](int kt, int buf) {
        const uint32_t dK = sbase + (AK_OFF + buf * 4352) * 4;
        const uint32_t dV = sbase + (AV_OFF + buf * 4608) * 4;
        #pragma unroll
        for (int i = 0; i < 4; i++) {
            int idx = tid + 256 * i, r = idx >> 4, c4 = idx & 15;
            cp_async16(dK + r * (68 * 4) + c4 * 16,
                       Kh + (size_t)(kt * 64 + r) * DK_ + c4 * 4);
            cp_async16(dV + r * (72 * 4) + c4 * 16,
                       Vh + (size_t)(kt * 64 + r) * DK_ + c4 * 4);
        }
        if (tid < 16)
            cp_async16(sbase + (AM_OFF + buf * 64) * 4 + tid * 16, mrow + kt * 64 + tid * 4);
        CP_COMMIT();
    };

    issue_kv(0, 0);
    #pragma unroll
    for (int i = 0; i < 8; i++) {
        int idx = tid + 256 * i, r = idx >> 4, c4 = idx & 15;
        *(float4*)(sQ + r * 68 + c4 * 4) = *(const float4*)(Qh + (size_t)(q0 + r) * DK_ + c4 * 4);
    }
    CP_WAIT(0);
    __syncthreads();

    float m0r = -1e30f, m1r = -1e30f, l0 = 0.0f, l1 = 0.0f;
    float co[8][4];
    #pragma unroll
    for (int nj = 0; nj < 8; nj++)
        #pragma unroll
        for (int q = 0; q < 4; q++) co[nj][q] = 0.0f;

    const unsigned FULL = 0xffffffffu;
    const int s0l = 4 * g + (t >> 1);
    const int s1l = s0l + 2;
    const int todd = t & 1;

    for (int kt = 0; kt < S_ / 64; kt++) {
        const int cur = kt & 1;
        const float* sK = sm + AK_OFF + cur * 4352;
        const float* sV = sm + AV_OFF + cur * 4608;
        const int*  sMk = (const int*)(sm + AM_OFF + cur * 64);

        if (kt + 1 < S_ / 64) issue_kv(kt + 1, cur ^ 1);

        float cs[8][4];
        #pragma unroll
        for (int nj = 0; nj < 8; nj++)
            #pragma unroll
            for (int q = 0; q < 4; q++) cs[nj][q] = 0.0f;

        #pragma unroll
        for (int ks = 0; ks < 8; ks++) {
            const int kb = ks * 8;
            uint32_t a[4];
            a[0] = to_tf32(sQ[(rowA    ) * 68 + kb + t    ]);
            a[1] = to_tf32(sQ[(rowA + 8) * 68 + kb + t    ]);
            a[2] = to_tf32(sQ[(rowA    ) * 68 + kb + t + 4]);
            a[3] = to_tf32(sQ[(rowA + 8) * 68 + kb + t + 4]);
            #pragma unroll
            for (int nj = 0; nj < 8; nj++) {
                uint32_t b0 = to_tf32(sK[(g + 8 * nj) * 68 + kb + t    ]);
                uint32_t b1 = to_tf32(sK[(g + 8 * nj) * 68 + kb + t + 4]);
                mma_tf32(cs[nj], a, b0, b1);
            }
        }

        float mx0 = -1e30f, mx1 = -1e30f;
        #pragma unroll
        for (int nj = 0; nj < 8; nj++) {
            const int c0m = sMk[8 * nj + 2 * t];
            const int c1m = sMk[8 * nj + 2 * t + 1];
            cs[nj][0] = c0m ? cs[nj][0] * 0.125f : -1e9f;
            cs[nj][1] = c1m ? cs[nj][1] * 0.125f : -1e9f;
            cs[nj][2] = c0m ? cs[nj][2] * 0.125f : -1e9f;
            cs[nj][3] = c1m ? cs[nj][3] * 0.125f : -1e9f;
            mx0 = fmaxf(mx0, fmaxf(cs[nj][0], cs[nj][1]));
            mx1 = fmaxf(mx1, fmaxf(cs[nj][2], cs[nj][3]));
        }
        #pragma unroll
        for (int d = 1; d < 4; d <<= 1) {
            mx0 = fmaxf(mx0, __shfl_xor_sync(FULL, mx0, d));
            mx1 = fmaxf(mx1, __shfl_xor_sync(FULL, mx1, d));
        }
        const float mn0 = fmaxf(m0r, mx0);
        const float mn1 = fmaxf(m1r, mx1);
        const float cr0 = __expf(m0r - mn0);
        const float cr1 = __expf(m1r - mn1);
        #pragma unroll
        for (int nj = 0; nj < 8; nj++) {
            co[nj][0] *= cr0; co[nj][1] *= cr0;
            co[nj][2] *= cr1; co[nj][3] *= cr1;
        }
        float ps0 = 0.0f, ps1 = 0.0f;
        #pragma unroll
        for (int nj = 0; nj < 8; nj++) {
            cs[nj][0] = __expf(cs[nj][0] - mn0);
            cs[nj][1] = __expf(cs[nj][1] - mn0);
            cs[nj][2] = __expf(cs[nj][2] - mn1);
            cs[nj][3] = __expf(cs[nj][3] - mn1);
            ps0 += cs[nj][0] + cs[nj][1];
            ps1 += cs[nj][2] + cs[nj][3];
        }
        #pragma unroll
        for (int d = 1; d < 4; d <<= 1) {
            ps0 += __shfl_xor_sync(FULL, ps0, d);
            ps1 += __shfl_xor_sync(FULL, ps1, d);
        }
        l0 = l0 * cr0 + ps0;
        l1 = l1 * cr1 + ps1;
        m0r = mn0; m1r = mn1;

        #pragma unroll
        for (int ks = 0; ks < 8; ks++) {
            float x0 = __shfl_sync(FULL, cs[ks][0], s0l);
            float x1 = __shfl_sync(FULL, cs[ks][1], s0l);
            float x2 = __shfl_sync(FULL, cs[ks][2], s0l);
            float x3 = __shfl_sync(FULL, cs[ks][3], s0l);
            float y0 = __shfl_sync(FULL, cs[ks][0], s1l);
            float y1 = __shfl_sync(FULL, cs[ks][1], s1l);
            float y2 = __shfl_sync(FULL, cs[ks][2], s1l);
            float y3 = __shfl_sync(FULL, cs[ks][3], s1l);
            uint32_t a[4];
            a[0] = to_tf32(todd ? x1 : x0);
            a[1] = to_tf32(todd ? x3 : x2);
            a[2] = to_tf32(todd ? y1 : y0);
            a[3] = to_tf32(todd ? y3 : y2);
            const int kb = ks * 8;
            #pragma unroll
            for (int nj = 0; nj < 8; nj++) {
                uint32_t b0 = to_tf32(sV[(kb + t    ) * 72 + 8 * nj + g]);
                uint32_t b1 = to_tf32(sV[(kb + t + 4) * 72 + 8 * nj + g]);
                mma_tf32(co[nj], a, b0, b1);
            }
        }

        if (kt + 1 < S_ / 64) CP_WAIT(0);
        __syncthreads();
    }

    const float inv0 = 1.0f / l0;
    const float inv1 = 1.0f / l1;
    #pragma unroll
    for (int nj = 0; nj < 8; nj++) {
        const int d = 8 * nj + 2 * t;
        float2 v0 = make_float2(co[nj][0] * inv0, co[nj][1] * inv0);
        float2 v1 = make_float2(co[nj][2] * inv1, co[nj][3] * inv1);
        *(float2*)(gx + ((size_t)b * S_ + q0 + rowA    ) * D_ + h * DK_ + d) = v0;
        *(float2*)(gx + ((size_t)b * S_ + q0 + rowA + 8) * D_ + h * DK_ + d) = v1;
    }
}

extern "C" void kernel_launch(void* const* d_in, const int* in_sizes, int n_in,
                              void* d_out, int out_size)
{
    const float* query = (const float*)d_in[0];
    const float* key_  = (const float*)d_in[1];
    const float* value = (const float*)d_in[2];
    const int*   mask  = (const int*)d_in[3];
    const float* Wq = (const float*)d_in[4];
    const float* bq = (const float*)d_in[5];
    const float* Wk = (const float*)d_in[6];
    const float* bk = (const float*)d_in[7];
    const float* Wv = (const float*)d_in[8];
    const float* bv = (const float*)d_in[9];
    const float* Wo = (const float*)d_in[10];
    const float* bo = (const float*)d_in[11];
    float* out = (float*)d_out;

    float *gq, *gk, *gv, *gx;
    cudaGetSymbolAddress((void**)&gq, g_q);
    cudaGetSymbolAddress((void**)&gk, g_k);
    cudaGetSymbolAddress((void**)&gv, g_v);
    cudaGetSymbolAddress((void**)&gx, g_x);

    cudaFuncSetAttribute(gemm_qkv, cudaFuncAttributeMaxDynamicSharedMemorySize, GK_SMEM);
    cudaFuncSetAttribute(gemm_out, cudaFuncAttributeMaxDynamicSharedMemorySize, GK_SMEM);
    cudaFuncSetAttribute(attn_mma, cudaFuncAttributeMaxDynamicSharedMemorySize, ATTN_SMEM_BYTES);

    dim3 gProj(D_ / 128, (B_ * S_) / 128, 3);   // (6, 64, 3)
    gemm_qkv<<<gProj, 256, GK_SMEM>>>(query, key_, value, Wq, bq, Wk, bk, Wv, bv, gq, gk, gv);

    dim3 gAttn(S_ / 128, H_, B_);               // (16, 12, 4)
    attn_mma<<<gAttn, 256, ATTN_SMEM_BYTES>>>(gq, gk, gv, mask, gx);

    dim3 gOut(D_ / 128, (B_ * S_) / 128);       // (6, 64)
    gemm_out<<<gOut, 256, GK_SMEM>>>(gx, Wo, bo, out);
}

// round 13
// speedup vs baseline: 5.9901x; 1.0278x over previous
#include <cuda_runtime.h>
#include <cstdint>

#define B_  4
#define S_  2048
#define D_  768
#define H_  12
#define DK_ 64

__device__ __forceinline__ uint32_t smem_u32(const void* p) {
    uint32_t a; asm("{ .reg .u64 t; cvta.to.shared.u64 t, %1; cvt.u32.u64 %0, t; }" : "=r"(a) : "l"(p));
    return a;
}
__device__ __forceinline__ void cp_async16(uint32_t dst, const void* src) {
    asm volatile("cp.async.cg.shared.global [%0], [%1], 16;" :: "r"(dst), "l"(src) : "memory");
}
#define CP_COMMIT() asm volatile("cp.async.commit_group;" ::: "memory")
#define CP_WAIT(n)  asm volatile("cp.async.wait_group %0;" :: "n"(n) : "memory")

// m16n8k8 tf32 mma (attention)
__device__ __forceinline__ void mma_tf32(float* c, const uint32_t* a, uint32_t b0, uint32_t b1) {
    asm volatile(
        "mma.sync.aligned.m16n8k8.row.col.f32.tf32.tf32.f32 "
        "{%0,%1,%2,%3}, {%4,%5,%6,%7}, {%8,%9}, {%0,%1,%2,%3};"
        : "+f"(c[0]), "+f"(c[1]), "+f"(c[2]), "+f"(c[3])
        : "r"(a[0]), "r"(a[1]), "r"(a[2]), "r"(a[3]), "r"(b0), "r"(b1));
}
// m16n8k16 bf16 mma (projections)
__device__ __forceinline__ void mma_bf16(float* c, const uint32_t* a, uint32_t b0, uint32_t b1) {
    asm volatile(
        "mma.sync.aligned.m16n8k16.row.col.f32.bf16.bf16.f32 "
        "{%0,%1,%2,%3}, {%4,%5,%6,%7}, {%8,%9}, {%0,%1,%2,%3};"
        : "+f"(c[0]), "+f"(c[1]), "+f"(c[2]), "+f"(c[3])
        : "r"(a[0]), "r"(a[1]), "r"(a[2]), "r"(a[3]), "r"(b0), "r"(b1));
}
// bf16x3 pack: hi = bf16x2(x0,x1) (low k in low half), lo = bf16x2 of exact residuals
__device__ __forceinline__ void bf16x3_pack(float x0, float x1, uint32_t& hi, uint32_t& lo) {
    asm("cvt.rn.bf16x2.f32 %0, %1, %2;" : "=r"(hi) : "f"(x1), "f"(x0));
    float h0 = __uint_as_float(hi << 16);
    float h1 = __uint_as_float(hi & 0xFFFF0000u);
    float r0 = x0 - h0;
    float r1 = x1 - h1;
    asm("cvt.rn.bf16x2.f32 %0, %1, %2;" : "=r"(lo) : "f"(r1), "f"(r0));
}
// round-to-nearest tf32
__device__ __forceinline__ uint32_t to_tf32(float x) {
    uint32_t r; asm("cvt.rna.tf32.f32 %0,%1;" : "=r"(r) : "f"(x)); return r;
}
__device__ __forceinline__ float4 round_tf32_4(float4 v) {
    v.x = __uint_as_float(to_tf32(v.x));
    v.y = __uint_as_float(to_tf32(v.y));
    v.z = __uint_as_float(to_tf32(v.z));
    v.w = __uint_as_float(to_tf32(v.w));
    return v;
}

// Scratch
__device__ float g_q[(size_t)B_ * H_ * S_ * DK_];
__device__ float g_k[(size_t)B_ * H_ * S_ * DK_];
__device__ float g_v[(size_t)B_ * H_ * S_ * DK_];
__device__ float g_x[(size_t)B_ * S_ * D_];

// ---------------------------------------------------------------------------
// bf16x3 GEMM body (unchanged from R12 — passed at rel_err 4.2e-4 total)
// ---------------------------------------------------------------------------
#define GK_PITCH 36
#define GK_MATF  (128 * GK_PITCH)
#define GK_MATB  (GK_MATF * 4)
#define GK_STAGEF (2 * GK_MATF)
#define GK_STAGEB (2 * GK_MATB)
#define GK_SMEM  (2 * GK_STAGEB)

__device__ __forceinline__ void gemm_body(
    const float* __restrict__ X, const float* __restrict__ W,
    const float* __restrict__ bias, float* __restrict__ out, int scatter)
{
    extern __shared__ float smf[];
    const uint32_t sbase = smem_u32(smf);
    const int tid = threadIdx.x;
    const int lane = tid & 31;
    const int wid = tid >> 5;
    const int wm = (wid & 3) * 32;
    const int wn = (wid >> 2) * 64;
    const int m0 = blockIdx.y * 128;
    const int n0 = blockIdx.x * 128;
    const int g = lane >> 2, t = lane & 3;

    float c[2][8][4];
    #pragma unroll
    for (int mi = 0; mi < 2; mi++)
        #pragma unroll
        for (int nj = 0; nj < 8; nj++)
            #pragma unroll
            for (int q = 0; q < 4; q++) c[mi][nj][q] = 0.0f;

    auto issue = [&](int ch) {
        const int k0 = ch * 32;
        const uint32_t dstA = sbase + (ch & 1) * GK_STAGEB;
        const uint32_t dstB = dstA + GK_MATB;
        #pragma unroll
        for (int i = 0; i < 4; i++) {
            int idx = tid + 256 * i;
            int r = idx >> 3, c4 = idx & 7;
            cp_async16(dstA + r * (GK_PITCH * 4) + c4 * 16,
                       X + (size_t)(m0 + r) * D_ + k0 + c4 * 4);
            cp_async16(dstB + r * (GK_PITCH * 4) + c4 * 16,
                       W + (size_t)(n0 + r) * D_ + k0 + c4 * 4);
        }
        CP_COMMIT();
    };

    issue(0);
    for (int ch = 0; ch < 24; ch++) {
        if (ch + 1 < 24) { issue(ch + 1); CP_WAIT(1); }
        else             { CP_WAIT(0); }
        __syncthreads();

        const float* sA = smf + (ch & 1) * GK_STAGEF;
        const float* sB = sA + GK_MATF;

        #pragma unroll
        for (int k16 = 0; k16 < 2; k16++) {
            const int kb = k16 * 16;
            uint32_t ah[2][4], al[2][4];
            #pragma unroll
            for (int mi = 0; mi < 2; mi++) {
                const int r0 = wm + mi * 16 + g;
                float2 p0 = *(const float2*)(sA + (r0    ) * GK_PITCH + kb + 2 * t);
                float2 p1 = *(const float2*)(sA + (r0 + 8) * GK_PITCH + kb + 2 * t);
                float2 p2 = *(const float2*)(sA + (r0    ) * GK_PITCH + kb + 2 * t + 8);
                float2 p3 = *(const float2*)(sA + (r0 + 8) * GK_PITCH + kb + 2 * t + 8);
                bf16x3_pack(p0.x, p0.y, ah[mi][0], al[mi][0]);
                bf16x3_pack(p1.x, p1.y, ah[mi][1], al[mi][1]);
                bf16x3_pack(p2.x, p2.y, ah[mi][2], al[mi][2]);
                bf16x3_pack(p3.x, p3.y, ah[mi][3], al[mi][3]);
            }
            #pragma unroll
            for (int nj = 0; nj < 8; nj++) {
                const int cn = wn + nj * 8 + g;
                float2 q0 = *(const float2*)(sB + cn * GK_PITCH + kb + 2 * t);
                float2 q1 = *(const float2*)(sB + cn * GK_PITCH + kb + 2 * t + 8);
                uint32_t bh0, bl0, bh1, bl1;
                bf16x3_pack(q0.x, q0.y, bh0, bl0);
                bf16x3_pack(q1.x, q1.y, bh1, bl1);
                mma_bf16(c[0][nj], ah[0], bh0, bh1);
                mma_bf16(c[0][nj], ah[0], bl0, bl1);
                mma_bf16(c[0][nj], al[0], bh0, bh1);
                mma_bf16(c[1][nj], ah[1], bh0, bh1);
                mma_bf16(c[1][nj], ah[1], bl0, bl1);
                mma_bf16(c[1][nj], al[1], bh0, bh1);
            }
        }
        __syncthreads();
    }

    #pragma unroll
    for (int nj = 0; nj < 8; nj++) {
        const int n = n0 + wn + nj * 8 + 2 * t;
        const float2 bb = *(const float2*)(bias + n);
        #pragma unroll
        for (int mi = 0; mi < 2; mi++) {
            #pragma unroll
            for (int half = 0; half < 2; half++) {
                const int m = m0 + wm + mi * 16 + g + 8 * half;
                float2 v;
                v.x = c[mi][nj][2 * half + 0] + bb.x;
                v.y = c[mi][nj][2 * half + 1] + bb.y;
                if (scatter) {
                    const int h = n >> 6, dk = n & 63;
                    const int bi = m >> 11, s = m & 2047;
                    *(float2*)(out + ((((size_t)bi * H_ + h) * S_) + s) * DK_ + dk) = v;
                } else {
                    *(float2*)(out + (size_t)m * D_ + n) = v;
                }
            }
        }
    }
}

__global__ __launch_bounds__(256, 2) void gemm_qkv(
    const float* __restrict__ q, const float* __restrict__ k, const float* __restrict__ v,
    const float* __restrict__ Wq, const float* __restrict__ bq,
    const float* __restrict__ Wk, const float* __restrict__ bk,
    const float* __restrict__ Wv, const float* __restrict__ bv,
    float* __restrict__ gq, float* __restrict__ gk, float* __restrict__ gv)
{
    const int z = blockIdx.z;
    const float* X  = (z == 0) ? q  : (z == 1) ? k  : v;
    const float* W  = (z == 0) ? Wq : (z == 1) ? Wk : Wv;
    const float* bb = (z == 0) ? bq : (z == 1) ? bk : bv;
    float* out      = (z == 0) ? gq : (z == 1) ? gk : gv;
    gemm_body(X, W, bb, out, 1);
}

__global__ __launch_bounds__(256, 2) void gemm_out(
    const float* __restrict__ X, const float* __restrict__ W,
    const float* __restrict__ bias, float* __restrict__ out)
{
    gemm_body(X, W, bias, out, 0);
}

// ---------------------------------------------------------------------------
// Tensor-core flash attention v4: operands pre-rounded to tf32 in SMEM
// (Q once at load; K/V in place after each cp.async wait — no extra barrier).
// Hot loops are pure LDS + MMA. Numerics bit-identical to v3.
// ---------------------------------------------------------------------------
#define AQ_OFF  0
#define AK_OFF  8704
#define AV_OFF  (AK_OFF + 2 * 4352)
#define AM_OFF  (AV_OFF + 2 * 4608)
#define ATTN_SMEM_BYTES ((AM_OFF + 128) * 4)

__global__ __launch_bounds__(256, 2) void attn_mma(
    const float* __restrict__ gq, const float* __restrict__ gk,
    const float* __restrict__ gv, const int* __restrict__ mask,
    float* __restrict__ gx)
{
    extern __shared__ float sm[];
    const uint32_t sbase = smem_u32(sm);
    float* sQ = sm + AQ_OFF;

    const int tid = threadIdx.x;
    const int wid = tid >> 5;
    const int lane = tid & 31;
    const int g = lane >> 2, t = lane & 3;
    const int q0 = blockIdx.x * 128;
    const int h  = blockIdx.y;
    const int b  = blockIdx.z;
    const int rowA = 16 * wid + g;

    const size_t hb = (((size_t)b * H_ + h) * S_) * DK_;
    const float* Qh = gq + hb;
    const float* Kh = gk + hb;
    const float* Vh = gv + hb;
    const int* mrow = mask + (size_t)b * S_;

    auto issue_kv = [&](int kt, int buf) {
        const uint32_t dK = sbase + (AK_OFF + buf * 4352) * 4;
        const uint32_t dV = sbase + (AV_OFF + buf * 4608) * 4;
        #pragma unroll
        for (int i = 0; i < 4; i++) {
            int idx = tid + 256 * i, r = idx >> 4, c4 = idx & 15;
            cp_async16(dK + r * (68 * 4) + c4 * 16,
                       Kh + (size_t)(kt * 64 + r) * DK_ + c4 * 4);
            cp_async16(dV + r * (72 * 4) + c4 * 16,
                       Vh + (size_t)(kt * 64 + r) * DK_ + c4 * 4);
        }
        if (tid < 16)
            cp_async16(sbase + (AM_OFF + buf * 64) * 4 + tid * 16, mrow + kt * 64 + tid * 4);
        CP_COMMIT();
    };

    // Round landed K/V buffer to tf32 in place (shared across all warps).
    auto round_kv = [&](int buf) {
        float* bK = sm + AK_OFF + buf * 4352;
        float* bV = sm + AV_OFF + buf * 4608;
        #pragma unroll
        for (int i = 0; i < 4; i++) {
            int idx = tid + 256 * i, r = idx >> 4, c4 = idx & 15;
            float4* pk = (float4*)(bK + r * 68 + c4 * 4);
            float4* pv = (float4*)(bV + r * 72 + c4 * 4);
            *pk = round_tf32_4(*pk);
            *pv = round_tf32_4(*pv);
        }
    };

    issue_kv(0, 0);
    // Q tile: round to tf32 during the load
    #pragma unroll
    for (int i = 0; i < 8; i++) {
        int idx = tid + 256 * i, r = idx >> 4, c4 = idx & 15;
        float4 qv = *(const float4*)(Qh + (size_t)(q0 + r) * DK_ + c4 * 4);
        *(float4*)(sQ + r * 68 + c4 * 4) = round_tf32_4(qv);
    }
    CP_WAIT(0);
    __syncthreads();          // K/V buf0 landed, raw
    round_kv(0);
    __syncthreads();          // buf0 rounded, visible to all warps

    float m0r = -1e30f, m1r = -1e30f, l0 = 0.0f, l1 = 0.0f;
    float co[8][4];
    #pragma unroll
    for (int nj = 0; nj < 8; nj++)
        #pragma unroll
        for (int q = 0; q < 4; q++) co[nj][q] = 0.0f;

    const unsigned FULL = 0xffffffffu;
    const int s0l = 4 * g + (t >> 1);
    const int s1l = s0l + 2;
    const int todd = t & 1;

    for (int kt = 0; kt < S_ / 64; kt++) {
        const int cur = kt & 1;
        const float* sK = sm + AK_OFF + cur * 4352;
        const float* sV = sm + AV_OFF + cur * 4608;
        const int*  sMk = (const int*)(sm + AM_OFF + cur * 64);

        if (kt + 1 < S_ / 64) issue_kv(kt + 1, cur ^ 1);

        // ---- QK^T (tf32, operands pre-rounded: pure LDS + MMA) ----
        float cs[8][4];
        #pragma unroll
        for (int nj = 0; nj < 8; nj++)
            #pragma unroll
            for (int q = 0; q < 4; q++) cs[nj][q] = 0.0f;

        #pragma unroll
        for (int ks = 0; ks < 8; ks++) {
            const int kb = ks * 8;
            uint32_t a[4];
            a[0] = __float_as_uint(sQ[(rowA    ) * 68 + kb + t    ]);
            a[1] = __float_as_uint(sQ[(rowA + 8) * 68 + kb + t    ]);
            a[2] = __float_as_uint(sQ[(rowA    ) * 68 + kb + t + 4]);
            a[3] = __float_as_uint(sQ[(rowA + 8) * 68 + kb + t + 4]);
            #pragma unroll
            for (int nj = 0; nj < 8; nj++) {
                uint32_t b0 = __float_as_uint(sK[(g + 8 * nj) * 68 + kb + t    ]);
                uint32_t b1 = __float_as_uint(sK[(g + 8 * nj) * 68 + kb + t + 4]);
                mma_tf32(cs[nj], a, b0, b1);
            }
        }

        // ---- mask + scale + online softmax ----
        float mx0 = -1e30f, mx1 = -1e30f;
        #pragma unroll
        for (int nj = 0; nj < 8; nj++) {
            const int c0m = sMk[8 * nj + 2 * t];
            const int c1m = sMk[8 * nj + 2 * t + 1];
            cs[nj][0] = c0m ? cs[nj][0] * 0.125f : -1e9f;
            cs[nj][1] = c1m ? cs[nj][1] * 0.125f : -1e9f;
            cs[nj][2] = c0m ? cs[nj][2] * 0.125f : -1e9f;
            cs[nj][3] = c1m ? cs[nj][3] * 0.125f : -1e9f;
            mx0 = fmaxf(mx0, fmaxf(cs[nj][0], cs[nj][1]));
            mx1 = fmaxf(mx1, fmaxf(cs[nj][2], cs[nj][3]));
        }
        #pragma unroll
        for (int d = 1; d < 4; d <<= 1) {
            mx0 = fmaxf(mx0, __shfl_xor_sync(FULL, mx0, d));
            mx1 = fmaxf(mx1, __shfl_xor_sync(FULL, mx1, d));
        }
        const float mn0 = fmaxf(m0r, mx0);
        const float mn1 = fmaxf(m1r, mx1);
        const float cr0 = __expf(m0r - mn0);
        const float cr1 = __expf(m1r - mn1);
        #pragma unroll
        for (int nj = 0; nj < 8; nj++) {
            co[nj][0] *= cr0; co[nj][1] *= cr0;
            co[nj][2] *= cr1; co[nj][3] *= cr1;
        }
        float ps0 = 0.0f, ps1 = 0.0f;
        #pragma unroll
        for (int nj = 0; nj < 8; nj++) {
            cs[nj][0] = __expf(cs[nj][0] - mn0);
            cs[nj][1] = __expf(cs[nj][1] - mn0);
            cs[nj][2] = __expf(cs[nj][2] - mn1);
            cs[nj][3] = __expf(cs[nj][3] - mn1);
            ps0 += cs[nj][0] + cs[nj][1];
            ps1 += cs[nj][2] + cs[nj][3];
        }
        #pragma unroll
        for (int d = 1; d < 4; d <<= 1) {
            ps0 += __shfl_xor_sync(FULL, ps0, d);
            ps1 += __shfl_xor_sync(FULL, ps1, d);
        }
        l0 = l0 * cr0 + ps0;
        l1 = l1 * cr1 + ps1;
        m0r = mn0; m1r = mn1;

        // ---- PV (tf32): P A-fragments via quad shuffles; V pre-rounded ----
        #pragma unroll
        for (int ks = 0; ks < 8; ks++) {
            float x0 = __shfl_sync(FULL, cs[ks][0], s0l);
            float x1 = __shfl_sync(FULL, cs[ks][1], s0l);
            float x2 = __shfl_sync(FULL, cs[ks][2], s0l);
            float x3 = __shfl_sync(FULL, cs[ks][3], s0l);
            float y0 = __shfl_sync(FULL, cs[ks][0], s1l);
            float y1 = __shfl_sync(FULL, cs[ks][1], s1l);
            float y2 = __shfl_sync(FULL, cs[ks][2], s1l);
            float y3 = __shfl_sync(FULL, cs[ks][3], s1l);
            uint32_t a[4];
            a[0] = to_tf32(todd ? x1 : x0);
            a[1] = to_tf32(todd ? x3 : x2);
            a[2] = to_tf32(todd ? y1 : y0);
            a[3] = to_tf32(todd ? y3 : y2);
            const int kb = ks * 8;
            #pragma unroll
            for (int nj = 0; nj < 8; nj++) {
                uint32_t b0 = __float_as_uint(sV[(kb + t    ) * 72 + 8 * nj + g]);
                uint32_t b1 = __float_as_uint(sV[(kb + t + 4) * 72 + 8 * nj + g]);
                mma_tf32(co[nj], a, b0, b1);
            }
        }

        if (kt + 1 < S_ / 64) {
            CP_WAIT(0);            // next K/V landed (raw)
            __syncthreads();       // all warps done reading cur buffers
            round_kv(cur ^ 1);     // round the idle (next) buffer in place
            __syncthreads();       // rounded data visible before next tile
        }
    }

    // ---- finalize ----
    const float inv0 = 1.0f / l0;
    const float inv1 = 1.0f / l1;
    #pragma unroll
    for (int nj = 0; nj < 8; nj++) {
        const int d = 8 * nj + 2 * t;
        float2 v0 = make_float2(co[nj][0] * inv0, co[nj][1] * inv0);
        float2 v1 = make_float2(co[nj][2] * inv1, co[nj][3] * inv1);
        *(float2*)(gx + ((size_t)b * S_ + q0 + rowA    ) * D_ + h * DK_ + d) = v0;
        *(float2*)(gx + ((size_t)b * S_ + q0 + rowA + 8) * D_ + h * DK_ + d) = v1;
    }
}

extern "C" void kernel_launch(void* const* d_in, const int* in_sizes, int n_in,
                              void* d_out, int out_size)
{
    const float* query = (const float*)d_in[0];
    const float* key_  = (const float*)d_in[1];
    const float* value = (const float*)d_in[2];
    const int*   mask  = (const int*)d_in[3];
    const float* Wq = (const float*)d_in[4];
    const float* bq = (const float*)d_in[5];
    const float* Wk = (const float*)d_in[6];
    const float* bk = (const float*)d_in[7];
    const float* Wv = (const float*)d_in[8];
    const float* bv = (const float*)d_in[9];
    const float* Wo = (const float*)d_in[10];
    const float* bo = (const float*)d_in[11];
    float* out = (float*)d_out;

    float *gq, *gk, *gv, *gx;
    cudaGetSymbolAddress((void**)&gq, g_q);
    cudaGetSymbolAddress((void**)&gk, g_k);
    cudaGetSymbolAddress((void**)&gv, g_v);
    cudaGetSymbolAddress((void**)&gx, g_x);

    cudaFuncSetAttribute(gemm_qkv, cudaFuncAttributeMaxDynamicSharedMemorySize, GK_SMEM);
    cudaFuncSetAttribute(gemm_out, cudaFuncAttributeMaxDynamicSharedMemorySize, GK_SMEM);
    cudaFuncSetAttribute(attn_mma, cudaFuncAttributeMaxDynamicSharedMemorySize, ATTN_SMEM_BYTES);

    dim3 gProj(D_ / 128, (B_ * S_) / 128, 3);   // (6, 64, 3)
    gemm_qkv<<<gProj, 256, GK_SMEM>>>(query, key_, value, Wq, bq, Wk, bk, Wv, bv, gq, gk, gv);

    dim3 gAttn(S_ / 128, H_, B_);               // (16, 12, 4)
    attn_mma<<<gAttn, 256, ATTN_SMEM_BYTES>>>(gq, gk, gv, mask, gx);

    dim3 gOut(D_ / 128, (B_ * S_) / 128);       // (6, 64)
    gemm_out<<<gOut, 256, GK_SMEM>>>(gx, Wo, bo, out);
}